// round 12
// baseline (speedup 1.0000x reference)
#include <cuda_runtime.h>
#include <cuda_bf16.h>

typedef unsigned long long ull;
#define BB 64
#define NENT 512

// ---------------- device scratch ----------------
__device__ float g_scat[BB*32*4096];   // zero-initialized at load; re-zeroed at end of each launch
__device__ float g_h1[BB*32*4096];
__device__ float g_h2[BB*64*1024];
__device__ float g_h3[BB*128*256];     // also reused as normalized o1 in res blocks
__device__ float g_h [BB*128*64];
__device__ float g_comb[BB*128*64];
__device__ float2 g_psum[128*8];
__device__ float g_partA[4*BB*128*64];
__device__ float g_partB[4*BB*128*64];
__device__ float g_pd2[2*BB*128*256];
__device__ float g_pd3[4*BB*128*64];
__device__ float g_wt1[32*16*64];
__device__ float g_wt2[64*16*128];
__device__ float g_wt3[128*16*128];
__device__ float g_rwt[8*128*9*128];

// ---------------- f32x2 helpers (bit-exact fp32 pairs) ----------------
__device__ __forceinline__ ull pk2(float v) {
    ull r; asm("mov.b64 %0, {%1,%2};" : "=l"(r) : "f"(v), "f"(v)); return r;
}
__device__ __forceinline__ void fma2(ull& d, ull a, ull b) {
    asm("fma.rn.f32x2 %0, %1, %2, %0;" : "+l"(d) : "l"(a), "l"(b));
}
__device__ __forceinline__ void upk(ull v, float& lo, float& hi) {
    asm("mov.b64 {%0,%1}, %2;" : "=f"(lo), "=f"(hi) : "l"(v));
}

// ---------------- small utility kernels ----------------
__global__ void k_zero4(float4* p) {
    p[blockIdx.x * 256 + threadIdx.x] = make_float4(0.f, 0.f, 0.f, 0.f);
}

// [co][ci][k16] -> [ci][k16][co]
template<int CIN, int COUT>
__global__ void k_tr_ds(const float* __restrict__ w, float* __restrict__ o) {
    int idx = blockIdx.x * 256 + threadIdx.x;
    if (idx >= CIN * 16 * COUT) return;
    int co = idx % COUT; int t = idx / COUT; int k = t % 16; int ci = t / 16;
    o[idx] = w[(co * CIN + ci) * 16 + k];
}

// res weights: [i][co][ci][k9] -> g_rwt[i'][(ci*9+k)*128+co]
__global__ void k_tr_res(const float* __restrict__ w1, const float* __restrict__ w2) {
    int idx = blockIdx.x * 256 + threadIdx.x;
    const int half = 589824;
    if (idx >= 2 * half) return;
    const float* s = (idx < half) ? w1 : w2;
    int id = (idx < half) ? idx : idx - half;
    int co = id & 127; int t = id >> 7; int k = t % 9; int t2 = t / 9;
    int ci = t2 & 127; int i = t2 >> 7;
    int dsti = (idx < half) ? i : (4 + i);
    g_rwt[(size_t)dsti * 147456 + (ci * 9 + k) * 128 + co] =
        s[(((size_t)i * 128 + co) * 128 + ci) * 9 + k];
}

// ---------------- scatter: warp per entity (g_scat pre-zeroed) ----------------
__global__ void k_scatter(const float* __restrict__ emb, const int* __restrict__ xy,
                          const float* __restrict__ w1) {
    __shared__ float s_wT[256 * 33];
    int tid = threadIdx.x;
    for (int i = tid; i < 32 * 256; i += blockDim.x) {
        int c = i >> 8, d = i & 255;
        s_wT[d * 33 + c] = w1[i];
    }
    __syncthreads();
    int warp = blockIdx.x * (blockDim.x >> 5) + (tid >> 5);
    int lane = tid & 31;
    if (warp >= BB * NENT) return;
    int b = warp / NENT, n = warp - b * NENT;
    const int* bits = xy + (size_t)(b * NENT + n) * 16;
    if (bits[0] == -1000000000) return;
    int bit = (lane < 16) ? bits[lane] : 0;
    int contrib;
    if (lane < 8)       contrib = bit << (7 - lane);
    else if (lane < 16) contrib = bit << (31 - lane);
    else                contrib = 0;
    int pack = __reduce_add_sync(0xffffffffu, contrib);
    int xv = (pack & 0xffff) >> 2;
    int yv = (pack >> 16) >> 2;
    const float4* e4 = reinterpret_cast<const float4*>(emb + (size_t)(b * NENT + n) * 256);
    float acc = 0.f;
#pragma unroll 8
    for (int i = 0; i < 64; i++) {
        float4 v = e4[i];
        acc += v.x * s_wT[(4 * i + 0) * 33 + lane];
        acc += v.y * s_wT[(4 * i + 1) * 33 + lane];
        acc += v.z * s_wT[(4 * i + 2) * 33 + lane];
        acc += v.w * s_wT[(4 * i + 3) * 33 + lane];
    }
    acc = fmaxf(acc, 0.f);
    if (acc != 0.f)
        atomicAdd(&g_scat[((size_t)b * 32 + lane) * 4096 + yv * 64 + xv], acc);
}

// ---------------- project 1x1: thread=pixel, all 32 co, f32x2 ----------------
__global__ __launch_bounds__(256)
void k_proj(const float* __restrict__ x, const float* __restrict__ pw,
            const float* __restrict__ pb) {
    __shared__ float s_w[50 * 32];   // [ci][co]
    __shared__ float s_b[32];
    int tid = threadIdx.x;
    for (int i = tid; i < 1600; i += 256) {
        int ci = i >> 5, co = i & 31;
        s_w[i] = pw[co * 50 + ci];
    }
    if (tid < 32) s_b[tid] = pb[tid];
    __syncthreads();
    int b = blockIdx.x >> 4;
    int p = ((blockIdx.x & 15) << 8) + tid;
    ull acc[16];
#pragma unroll
    for (int g = 0; g < 16; g++) acc[g] = 0ull;
    const float* srcs = g_scat + (size_t)b * 32 * 4096 + p;
#pragma unroll 1
    for (int ci = 0; ci < 32; ci++) {
        ull vp = pk2(srcs[ci * 4096]);
        const ulonglong2* wrow = reinterpret_cast<const ulonglong2*>(&s_w[ci * 32]);
#pragma unroll
        for (int gg = 0; gg < 8; gg++) {
            ulonglong2 w2 = wrow[gg];
            fma2(acc[2 * gg], vp, w2.x);
            fma2(acc[2 * gg + 1], vp, w2.y);
        }
    }
    const float* srcx = x + (size_t)b * 18 * 4096 + p;
#pragma unroll 1
    for (int cx = 0; cx < 18; cx++) {
        ull vp = pk2(srcx[cx * 4096]);
        const ulonglong2* wrow = reinterpret_cast<const ulonglong2*>(&s_w[(32 + cx) * 32]);
#pragma unroll
        for (int gg = 0; gg < 8; gg++) {
            ulonglong2 w2 = wrow[gg];
            fma2(acc[2 * gg], vp, w2.x);
            fma2(acc[2 * gg + 1], vp, w2.y);
        }
    }
    float* dst = g_h1 + (size_t)b * 32 * 4096 + p;
#pragma unroll
    for (int g = 0; g < 16; g++) {
        float lo, hi; upk(acc[g], lo, hi);
        dst[(2 * g) * 4096]     = fmaxf(lo + s_b[2 * g], 0.f);
        dst[(2 * g + 1) * 4096] = fmaxf(hi + s_b[2 * g + 1], 0.f);
    }
}

// ---------------- down conv k=4 s=2 p=1, f32x2; CSPLIT>1 -> raw partials ----------------
template<int CIN, int HIN, int COUT, int TCO, int TOW, int TOH, int CC, int NTHR, int CSPLIT>
__global__ __launch_bounds__(NTHR, 6)
void k_down(const float* __restrict__ in, const float* __restrict__ wT,
            const float* __restrict__ bias, float* __restrict__ out,
            float* __restrict__ out2) {
    constexpr int HO    = HIN / 2;
    constexpr int NCOG  = COUT / TCO;
    constexpr int NROWS = 2 * TOH + 2;
    constexpr int NP    = TCO / 2;
    constexpr int CLEN  = CIN / CSPLIT;
    static_assert(NTHR == NCOG * (HO / TOW), "thread count");
    __shared__ float s_in[NROWS * CC * HIN];
    __shared__ float s_w[CC * 16 * COUT];
    const int tid = threadIdx.x;
    const int b = blockIdx.y, oh0 = blockIdx.x * TOH;
    const int cibase = blockIdx.z * CLEN;
    const int cog = tid % NCOG, owg = tid / NCOG;
    const int co0 = TCO * cog, ow0 = owg * TOW;
    const int ihb = 2 * oh0 - 1;
    ull acc[NP][TOH][TOW];
#pragma unroll
    for (int p = 0; p < NP; p++)
#pragma unroll
        for (int o = 0; o < TOH; o++)
#pragma unroll
            for (int w = 0; w < TOW; w++) acc[p][o][w] = 0ull;

#pragma unroll 1
    for (int c0 = 0; c0 < CLEN; c0 += CC) {
        int ci0 = cibase + c0;
        __syncthreads();
        for (int i = tid; i < NROWS * CC * (HIN / 4); i += NTHR) {
            int r   = i / (CC * (HIN / 4));
            int rem = i - r * (CC * (HIN / 4));
            int cc  = rem / (HIN / 4);
            int x4  = rem - cc * (HIN / 4);
            int ih  = ihb + r;
            float4 v = make_float4(0.f, 0.f, 0.f, 0.f);
            if (ih >= 0 && ih < HIN)
                v = *reinterpret_cast<const float4*>(
                    &in[(((size_t)b * CIN + ci0 + cc) * HIN + ih) * HIN + 4 * x4]);
            *reinterpret_cast<float4*>(&s_in[(r * CC + cc) * HIN + 4 * x4]) = v;
        }
        const float4* wsrc = reinterpret_cast<const float4*>(wT + (size_t)ci0 * 16 * COUT);
        float4* wdst = reinterpret_cast<float4*>(s_w);
        for (int i = tid; i < CC * 16 * COUT / 4; i += NTHR) wdst[i] = wsrc[i];
        __syncthreads();
#pragma unroll 1
        for (int cc = 0; cc < CC; cc++) {
#pragma unroll
            for (int r = 0; r < NROWS; r++) {
                const float* row = &s_in[(r * CC + cc) * HIN];
                ull xd[2 * TOW + 2];
#pragma unroll
                for (int j = 0; j < 2 * TOW + 2; j++) {
                    int iw = 2 * ow0 - 1 + j;
                    float v = (iw >= 0 && iw < HIN) ? row[iw] : 0.f;
                    xd[j] = pk2(v);
                }
#pragma unroll
                for (int ot = 0; ot < TOH; ot++) {
                    int kh = r - 2 * ot;
                    if (kh >= 0 && kh < 4) {
                        ull wpk[NP][4];
#pragma unroll
                        for (int kw = 0; kw < 4; kw++) {
                            int idx = (cc * 16 + kh * 4 + kw) * COUT + co0;
                            if constexpr (NP == 2) {
                                ulonglong2 t = *reinterpret_cast<const ulonglong2*>(&s_w[idx]);
                                wpk[0][kw] = t.x; wpk[1][kw] = t.y;
                            } else {
                                wpk[0][kw] = *reinterpret_cast<const ull*>(&s_w[idx]);
                            }
                        }
#pragma unroll
                        for (int w = 0; w < TOW; w++)
#pragma unroll
                            for (int kw = 0; kw < 4; kw++)
#pragma unroll
                                for (int p = 0; p < NP; p++)
                                    fma2(acc[p][ot][w], xd[2 * w + kw], wpk[p][kw]);
                    }
                }
            }
        }
    }
    if constexpr (CSPLIT == 1) {
#pragma unroll
        for (int p = 0; p < NP; p++) {
            float bv0 = bias[co0 + 2 * p], bv1 = bias[co0 + 2 * p + 1];
#pragma unroll
            for (int ot = 0; ot < TOH; ot++)
#pragma unroll
                for (int w = 0; w < TOW; w++) {
                    float lo, hi; upk(acc[p][ot][w], lo, hi);
                    float v0 = fmaxf(lo + bv0, 0.f);
                    float v1 = fmaxf(hi + bv1, 0.f);
                    size_t o0 = (((size_t)b * COUT + co0 + 2 * p) * HO + oh0 + ot) * HO + ow0 + w;
                    out[o0] = v0;
                    out[o0 + (size_t)HO * HO] = v1;
                    if (out2) { out2[o0] = v0; out2[o0 + (size_t)HO * HO] = v1; }
                }
        }
    } else {
        float* dstp = out + (size_t)blockIdx.z * BB * COUT * HO * HO;
#pragma unroll
        for (int p = 0; p < NP; p++)
#pragma unroll
            for (int ot = 0; ot < TOH; ot++)
#pragma unroll
                for (int w = 0; w < TOW; w++) {
                    float lo, hi; upk(acc[p][ot][w], lo, hi);
                    size_t o0 = (((size_t)b * COUT + co0 + 2 * p) * HO + oh0 + ot) * HO + ow0 + w;
                    dstp[o0] = lo;
                    dstp[o0 + (size_t)HO * HO] = hi;
                }
    }
}

// ---------------- ds2 combine: 2 partials + bias + relu -> h3 ----------------
__global__ __launch_bounds__(256)
void k_comb2(const float* __restrict__ part, const float* __restrict__ bias,
             float* __restrict__ o) {
    int idx = blockIdx.x * 256 + threadIdx.x;   // over 64*128*256
    int c = (idx >> 8) & 127;
    o[idx] = fmaxf(part[idx] + part[2097152 + idx] + bias[c], 0.f);
}

// ---------------- ds3 combine: 4 partials + bias + relu -> g_h and d_out ----------------
__global__ __launch_bounds__(256)
void k_comb3(const float* __restrict__ part, const float* __restrict__ bias,
             float* __restrict__ hh, float* __restrict__ out) {
    int idx = blockIdx.x * 256 + threadIdx.x;   // over 64*128*64
    int c = (idx >> 6) & 127;
    float v = fmaxf(part[idx] + part[524288 + idx] + part[1048576 + idx]
                    + part[1572864 + idx] + bias[c], 0.f);
    hh[idx] = v;
    out[idx] = v;
}

// ---------------- res conv 3x3 p1 on 8x8: 2 co/thread, 32co blocks, zi=4 ----------------
__global__ __launch_bounds__(128, 6)
void k_res(const float* __restrict__ in, const float* __restrict__ wT,
           float* __restrict__ part) {
    __shared__ float s_img[16 * 100];
    __shared__ float s_w[16 * 9 * 32];   // [ciL][k][32 co]
    const int tid = threadIdx.x;
    const int b = blockIdx.y;
    const int co_base = blockIdx.x * 32;
    const int zi = blockIdx.z;
    const int copl = tid & 15, ohp = tid >> 4;
    const int co0 = co_base + 2 * copl;
    ull acc[8];
#pragma unroll
    for (int w = 0; w < 8; w++) acc[w] = 0ull;

#pragma unroll 1
    for (int c2 = 0; c2 < 2; c2++) {
        int cib = zi * 32 + c2 * 16;
        __syncthreads();
        for (int i = tid; i < 16 * 36; i += 128) {
            int ci = i / 36, e = i - 36 * ci;
            int ofs;
            if (e < 10)      ofs = e;
            else if (e < 20) ofs = 90 + (e - 10);
            else { int r = ((e - 20) >> 1) + 1; int c = ((e - 20) & 1) * 9; ofs = r * 10 + c; }
            s_img[ci * 100 + ofs] = 0.f;
        }
        {
            int ci = tid >> 3, r = tid & 7;
            const float4* src = reinterpret_cast<const float4*>(
                in + (((size_t)(b * 128 + cib + ci)) * 8 + r) * 8);
            float4 v0 = src[0], v1 = src[1];
            float* d = &s_img[ci * 100 + (r + 1) * 10 + 1];
            d[0] = v0.x; d[1] = v0.y; d[2] = v0.z; d[3] = v0.w;
            d[4] = v1.x; d[5] = v1.y; d[6] = v1.z; d[7] = v1.w;
        }
        for (int i = tid; i < 16 * 9 * 8; i += 128) {
            int c8 = i & 7; int t = i >> 3; int k = t % 9; int ciL = t / 9;
            *reinterpret_cast<float4*>(&s_w[(ciL * 9 + k) * 32 + 4 * c8]) =
                *reinterpret_cast<const float4*>(
                    wT + ((size_t)(cib + ciL) * 9 + k) * 128 + co_base + 4 * c8);
        }
        __syncthreads();
#pragma unroll 1
        for (int ciL = 0; ciL < 16; ciL++) {
            ull wp[9];
#pragma unroll
            for (int k = 0; k < 9; k++)
                wp[k] = *reinterpret_cast<const ull*>(&s_w[(ciL * 9 + k) * 32 + 2 * copl]);
#pragma unroll
            for (int kh = 0; kh < 3; kh++) {
                const float* row = &s_img[ciL * 100 + (ohp + kh) * 10];
                ull xd[10];
#pragma unroll
                for (int j = 0; j < 10; j++) xd[j] = pk2(row[j]);
#pragma unroll
                for (int ow = 0; ow < 8; ow++)
#pragma unroll
                    for (int kw = 0; kw < 3; kw++)
                        fma2(acc[ow], xd[ow + kw], wp[kh * 3 + kw]);
            }
        }
    }
    float* dst = part + (size_t)zi * 524288 + ((size_t)(b * 128 + co0)) * 64 + ohp * 8;
#pragma unroll
    for (int ow = 0; ow < 8; ow++) {
        float lo, hi; upk(acc[ow], lo, hi);
        dst[ow] = lo; dst[64 + ow] = hi;
    }
}

// ---------------- stage A: combine 4 partials, per-(channel,slice) stats ----------------
__global__ __launch_bounds__(256)
void k_pstats(const float* __restrict__ part) {
    int c = blockIdx.x, s = blockIdx.y, tid = threadIdx.x;
    float sum = 0.f, sq = 0.f;
#pragma unroll
    for (int t = 0; t < 2; t++) {
        int i = s * 512 + t * 256 + tid;       // i = b*64 + p
        int b = i >> 6, p = i & 63;
        size_t idx = ((size_t)(b * 128 + c)) * 64 + p;
        float v = part[idx] + part[524288 + idx] + part[1048576 + idx] + part[1572864 + idx];
        g_comb[idx] = v;
        sum += v; sq += v * v;
    }
    __shared__ float rs[256], rs2[256];
    rs[tid] = sum; rs2[tid] = sq;
    __syncthreads();
    for (int o = 128; o > 0; o >>= 1) {
        if (tid < o) { rs[tid] += rs[tid + o]; rs2[tid] += rs2[tid + o]; }
        __syncthreads();
    }
    if (tid == 0) g_psum[c * 8 + s] = make_float2(rs[0], rs2[0]);
}

// ---------------- stage B: fold psum -> scale/shift, normalize + relu ----------------
__global__ __launch_bounds__(256)
void k_norm(const float* __restrict__ gamma, const float* __restrict__ beta,
            float* __restrict__ o1) {
    int idx = blockIdx.x * 256 + threadIdx.x;
    int c = (idx >> 6) & 127;
    float s = 0.f, s2 = 0.f;
#pragma unroll
    for (int q = 0; q < 8; q++) {
        float2 v = g_psum[c * 8 + q];
        s += v.x; s2 += v.y;
    }
    float mean = s / 4096.f;
    float var  = s2 / 4096.f - mean * mean;
    float sc   = gamma[c] * rsqrtf(var + 1e-5f);
    float sh   = beta[c] - mean * sc;
    o1[idx] = fmaxf(fmaf(sc, g_comb[idx], sh), 0.f);
}

// ---------------- stage B': fold psum, normalize + residual + relu; g_h, map_skip ----------------
__global__ __launch_bounds__(256)
void k_applyres(const float* __restrict__ gamma, const float* __restrict__ beta,
                float* __restrict__ dskip) {
    int idx = blockIdx.x * 256 + threadIdx.x;
    int c = (idx >> 6) & 127;
    float s = 0.f, s2 = 0.f;
#pragma unroll
    for (int q = 0; q < 8; q++) {
        float2 v = g_psum[c * 8 + q];
        s += v.x; s2 += v.y;
    }
    float mean = s / 4096.f;
    float var  = s2 / 4096.f - mean * mean;
    float sc   = gamma[c] * rsqrtf(var + 1e-5f);
    float sh   = beta[c] - mean * sc;
    float h = fmaxf(fmaf(sc, g_comb[idx], sh) + g_h[idx], 0.f);
    g_h[idx] = h;
    dskip[idx] += h;
}

// ---------------- fc: 4 b rows in dynamic smem, 32 j per block ----------------
__global__ __launch_bounds__(256)
void k_fc(const float* __restrict__ w, const float* __restrict__ bias,
          float* __restrict__ outp) {
    extern __shared__ float s_a[];   // 4 * 8192
    int b0 = blockIdx.y * 4;
    int tid = threadIdx.x;
    float4* sd = reinterpret_cast<float4*>(s_a);
    const float4* src = reinterpret_cast<const float4*>(g_h + (size_t)b0 * 8192);
    for (int i = tid; i < 8192; i += 256) sd[i] = src[i];
    __syncthreads();
    int wrp = tid >> 5, lane = tid & 31;
#pragma unroll 1
    for (int q = 0; q < 4; q++) {
        int j = blockIdx.x * 32 + wrp * 4 + q;
        const float4* wr = reinterpret_cast<const float4*>(w + (size_t)j * 8192);
        float acc[4];
#pragma unroll
        for (int bl = 0; bl < 4; bl++) acc[bl] = 0.f;
#pragma unroll 2
        for (int i = lane; i < 2048; i += 32) {
            float4 wv = wr[i];
#pragma unroll
            for (int bl = 0; bl < 4; bl++) {
                float4 av = sd[bl * 2048 + i];
                acc[bl] += wv.x * av.x + wv.y * av.y + wv.z * av.z + wv.w * av.w;
            }
        }
#pragma unroll
        for (int o = 16; o > 0; o >>= 1)
#pragma unroll
            for (int bl = 0; bl < 4; bl++)
                acc[bl] += __shfl_down_sync(0xffffffffu, acc[bl], o);
        if (lane == 0) {
            float bv = bias[j];
#pragma unroll
            for (int bl = 0; bl < 4; bl++)
                outp[(size_t)(b0 + bl) * 256 + j] = fmaxf(acc[bl] + bv, 0.f);
        }
    }
}

// ---------------- launch ----------------
extern "C" void kernel_launch(void* const* d_in, const int* in_sizes, int n_in,
                              void* d_out, int out_size) {
    const float* x    = (const float*)d_in[0];
    const float* emb  = (const float*)d_in[1];
    const int*   xy   = (const int*)  d_in[2];
    const float* c1w  = (const float*)d_in[3];
    const float* pw   = (const float*)d_in[4];
    const float* pb   = (const float*)d_in[5];
    const float* ds1w = (const float*)d_in[6];
    const float* ds1b = (const float*)d_in[7];
    const float* ds2w = (const float*)d_in[8];
    const float* ds2b = (const float*)d_in[9];
    const float* ds3w = (const float*)d_in[10];
    const float* ds3b = (const float*)d_in[11];
    const float* rc1w = (const float*)d_in[12];
    const float* bn1g = (const float*)d_in[13];
    const float* bn1b = (const float*)d_in[14];
    const float* rc2w = (const float*)d_in[15];
    const float* bn2g = (const float*)d_in[16];
    const float* bn2b = (const float*)d_in[17];
    const float* fcw  = (const float*)d_in[18];
    const float* fcb  = (const float*)d_in[19];
    float* out = (float*)d_out;

    float *scat, *h1, *h2, *h3, *hh, *pA, *pB, *pd2, *pd3, *wt1, *wt2, *wt3, *rwt;
    cudaGetSymbolAddress((void**)&scat, g_scat);
    cudaGetSymbolAddress((void**)&h1,   g_h1);
    cudaGetSymbolAddress((void**)&h2,   g_h2);
    cudaGetSymbolAddress((void**)&h3,   g_h3);
    cudaGetSymbolAddress((void**)&hh,   g_h);
    cudaGetSymbolAddress((void**)&pA,   g_partA);
    cudaGetSymbolAddress((void**)&pB,   g_partB);
    cudaGetSymbolAddress((void**)&pd2,  g_pd2);
    cudaGetSymbolAddress((void**)&pd3,  g_pd3);
    cudaGetSymbolAddress((void**)&wt1,  g_wt1);
    cudaGetSymbolAddress((void**)&wt2,  g_wt2);
    cudaGetSymbolAddress((void**)&wt3,  g_wt3);
    cudaGetSymbolAddress((void**)&rwt,  g_rwt);

    cudaFuncSetAttribute((const void*)k_fc, cudaFuncAttributeMaxDynamicSharedMemorySize, 131072);

    // order chosen so launch #4 (profiled slot) = ds1
    k_tr_ds<32, 64><<<(32 * 16 * 64 + 255) / 256, 256>>>(ds1w, wt1);          // 1
    k_scatter<<<(BB * NENT) / 8, 256>>>(emb, xy, c1w);                        // 2 (g_scat pre-zeroed)
    k_proj<<<1024, 256>>>(x, pw, pb);                                         // 3
    // ds1: converged shape; launch_bounds(.,6) squeezes regs for 6 blocks/SM
    k_down<32, 64, 64, 4, 4, 2, 4, 128, 1><<<dim3(16, BB), 128>>>(h1, wt1, ds1b, h2, nullptr); // 4 <- profiled

    k_tr_ds<64, 128> <<<(64 * 16 * 128 + 255) / 256, 256>>>(ds2w, wt2);
    k_tr_ds<128, 128><<<(128 * 16 * 128 + 255) / 256, 256>>>(ds3w, wt3);
    k_tr_res<<<(2 * 589824 + 255) / 256, 256>>>(rc1w, rc2w);

    // ds2: ci-split x2 -> 1024 blocks, combine
    k_down<64, 32, 128, 4, 4, 2, 4, 128, 2><<<dim3(8, BB, 2), 128>>>(h2, wt2, nullptr, pd2, nullptr);
    k_comb2<<<8192, 256>>>(pd2, ds2b, h3);
    // ds3: ci-split x4 -> 1024 blocks, combine (writes g_h and map_skip init)
    k_down<128, 16, 128, 2, 4, 2, 4, 128, 4><<<dim3(4, BB, 4), 128>>>(h3, wt3, nullptr, pd3, nullptr);
    k_comb3<<<2048, 256>>>(pd3, ds3b, hh, out);

    for (int i = 0; i < 4; i++) {
        k_res<<<dim3(4, BB, 4), 128>>>(hh, rwt + (size_t)i * 147456, pA);
        k_pstats<<<dim3(128, 8), 256>>>(pA);
        k_norm<<<2048, 256>>>(bn1g + i * 128, bn1b + i * 128, h3);   // h3 reused as o1
        k_res<<<dim3(4, BB, 4), 128>>>(h3, rwt + (size_t)(4 + i) * 147456, pB);
        k_pstats<<<dim3(128, 8), 256>>>(pB);
        k_applyres<<<2048, 256>>>(bn2g + i * 128, bn2b + i * 128, out);
    }

    k_fc<<<dim3(8, 16), 256, 131072>>>(fcw, fcb, out + (size_t)BB * 128 * 64);

    // re-zero scatter buffer for the next invocation (replay-safe)
    k_zero4<<<8192, 256>>>(reinterpret_cast<float4*>(scat));
}

// round 13
// speedup vs baseline: 1.1340x; 1.1340x over previous
#include <cuda_runtime.h>
#include <cuda_bf16.h>

typedef unsigned long long ull;
#define BB 64
#define NENT 512

// ---------------- device scratch ----------------
__device__ float g_scat[BB*32*4096];   // zero-initialized at load; re-zeroed at end of each launch
__device__ float g_h1[BB*32*4096];
__device__ float g_h2[BB*64*1024];
__device__ float g_h3[BB*128*256];     // also reused as normalized o1 in res blocks
__device__ float g_h [BB*128*64];
__device__ float g_comb[BB*128*64];
__device__ float2 g_psum[128*8];
__device__ float g_partA[4*BB*128*64];
__device__ float g_partB[4*BB*128*64];
__device__ float g_pd1[2*BB*64*1024];
__device__ float g_pd2[2*BB*128*256];
__device__ float g_pd3[4*BB*128*64];
__device__ float g_wt1[32*16*64];
__device__ float g_wt2[64*16*128];
__device__ float g_wt3[128*16*128];
__device__ float g_rwt[8*128*9*128];

// ---------------- f32x2 helpers (bit-exact fp32 pairs) ----------------
__device__ __forceinline__ ull pk2(float v) {
    ull r; asm("mov.b64 %0, {%1,%2};" : "=l"(r) : "f"(v), "f"(v)); return r;
}
__device__ __forceinline__ void fma2(ull& d, ull a, ull b) {
    asm("fma.rn.f32x2 %0, %1, %2, %0;" : "+l"(d) : "l"(a), "l"(b));
}
__device__ __forceinline__ void upk(ull v, float& lo, float& hi) {
    asm("mov.b64 {%0,%1}, %2;" : "=f"(lo), "=f"(hi) : "l"(v));
}

// ---------------- small utility kernels ----------------
__global__ void k_zero4(float4* p) {
    p[blockIdx.x * 256 + threadIdx.x] = make_float4(0.f, 0.f, 0.f, 0.f);
}

// [co][ci][k16] -> [ci][k16][co]
template<int CIN, int COUT>
__global__ void k_tr_ds(const float* __restrict__ w, float* __restrict__ o) {
    int idx = blockIdx.x * 256 + threadIdx.x;
    if (idx >= CIN * 16 * COUT) return;
    int co = idx % COUT; int t = idx / COUT; int k = t % 16; int ci = t / 16;
    o[idx] = w[(co * CIN + ci) * 16 + k];
}

// res weights: [i][co][ci][k9] -> g_rwt[i'][(ci*9+k)*128+co]
__global__ void k_tr_res(const float* __restrict__ w1, const float* __restrict__ w2) {
    int idx = blockIdx.x * 256 + threadIdx.x;
    const int half = 589824;
    if (idx >= 2 * half) return;
    const float* s = (idx < half) ? w1 : w2;
    int id = (idx < half) ? idx : idx - half;
    int co = id & 127; int t = id >> 7; int k = t % 9; int t2 = t / 9;
    int ci = t2 & 127; int i = t2 >> 7;
    int dsti = (idx < half) ? i : (4 + i);
    g_rwt[(size_t)dsti * 147456 + (ci * 9 + k) * 128 + co] =
        s[(((size_t)i * 128 + co) * 128 + ci) * 9 + k];
}

// ---------------- scatter: warp per entity (g_scat pre-zeroed) ----------------
__global__ void k_scatter(const float* __restrict__ emb, const int* __restrict__ xy,
                          const float* __restrict__ w1) {
    __shared__ float s_wT[256 * 33];
    int tid = threadIdx.x;
    for (int i = tid; i < 32 * 256; i += blockDim.x) {
        int c = i >> 8, d = i & 255;
        s_wT[d * 33 + c] = w1[i];
    }
    __syncthreads();
    int warp = blockIdx.x * (blockDim.x >> 5) + (tid >> 5);
    int lane = tid & 31;
    if (warp >= BB * NENT) return;
    int b = warp / NENT, n = warp - b * NENT;
    const int* bits = xy + (size_t)(b * NENT + n) * 16;
    if (bits[0] == -1000000000) return;
    int bit = (lane < 16) ? bits[lane] : 0;
    int contrib;
    if (lane < 8)       contrib = bit << (7 - lane);
    else if (lane < 16) contrib = bit << (31 - lane);
    else                contrib = 0;
    int pack = __reduce_add_sync(0xffffffffu, contrib);
    int xv = (pack & 0xffff) >> 2;
    int yv = (pack >> 16) >> 2;
    const float4* e4 = reinterpret_cast<const float4*>(emb + (size_t)(b * NENT + n) * 256);
    float acc = 0.f;
#pragma unroll 8
    for (int i = 0; i < 64; i++) {
        float4 v = e4[i];
        acc += v.x * s_wT[(4 * i + 0) * 33 + lane];
        acc += v.y * s_wT[(4 * i + 1) * 33 + lane];
        acc += v.z * s_wT[(4 * i + 2) * 33 + lane];
        acc += v.w * s_wT[(4 * i + 3) * 33 + lane];
    }
    acc = fmaxf(acc, 0.f);
    if (acc != 0.f)
        atomicAdd(&g_scat[((size_t)b * 32 + lane) * 4096 + yv * 64 + xv], acc);
}

// ---------------- project 1x1: thread=pixel, all 32 co, f32x2 ----------------
__global__ __launch_bounds__(256)
void k_proj(const float* __restrict__ x, const float* __restrict__ pw,
            const float* __restrict__ pb) {
    __shared__ float s_w[50 * 32];   // [ci][co]
    __shared__ float s_b[32];
    int tid = threadIdx.x;
    for (int i = tid; i < 1600; i += 256) {
        int ci = i >> 5, co = i & 31;
        s_w[i] = pw[co * 50 + ci];
    }
    if (tid < 32) s_b[tid] = pb[tid];
    __syncthreads();
    int b = blockIdx.x >> 4;
    int p = ((blockIdx.x & 15) << 8) + tid;
    ull acc[16];
#pragma unroll
    for (int g = 0; g < 16; g++) acc[g] = 0ull;
    const float* srcs = g_scat + (size_t)b * 32 * 4096 + p;
#pragma unroll 1
    for (int ci = 0; ci < 32; ci++) {
        ull vp = pk2(srcs[ci * 4096]);
        const ulonglong2* wrow = reinterpret_cast<const ulonglong2*>(&s_w[ci * 32]);
#pragma unroll
        for (int gg = 0; gg < 8; gg++) {
            ulonglong2 w2 = wrow[gg];
            fma2(acc[2 * gg], vp, w2.x);
            fma2(acc[2 * gg + 1], vp, w2.y);
        }
    }
    const float* srcx = x + (size_t)b * 18 * 4096 + p;
#pragma unroll 1
    for (int cx = 0; cx < 18; cx++) {
        ull vp = pk2(srcx[cx * 4096]);
        const ulonglong2* wrow = reinterpret_cast<const ulonglong2*>(&s_w[(32 + cx) * 32]);
#pragma unroll
        for (int gg = 0; gg < 8; gg++) {
            ulonglong2 w2 = wrow[gg];
            fma2(acc[2 * gg], vp, w2.x);
            fma2(acc[2 * gg + 1], vp, w2.y);
        }
    }
    float* dst = g_h1 + (size_t)b * 32 * 4096 + p;
#pragma unroll
    for (int g = 0; g < 16; g++) {
        float lo, hi; upk(acc[g], lo, hi);
        dst[(2 * g) * 4096]     = fmaxf(lo + s_b[2 * g], 0.f);
        dst[(2 * g + 1) * 4096] = fmaxf(hi + s_b[2 * g + 1], 0.f);
    }
}

// ---------------- down conv k=4 s=2 p=1, f32x2; CSPLIT>1 -> raw partials ----------------
template<int CIN, int HIN, int COUT, int TCO, int TOW, int TOH, int CC, int NTHR, int CSPLIT>
__global__ __launch_bounds__(NTHR)
void k_down(const float* __restrict__ in, const float* __restrict__ wT,
            const float* __restrict__ bias, float* __restrict__ out,
            float* __restrict__ out2) {
    constexpr int HO    = HIN / 2;
    constexpr int NCOG  = COUT / TCO;
    constexpr int NROWS = 2 * TOH + 2;
    constexpr int NP    = TCO / 2;
    constexpr int CLEN  = CIN / CSPLIT;
    static_assert(NTHR == NCOG * (HO / TOW), "thread count");
    __shared__ float s_in[NROWS * CC * HIN];
    __shared__ float s_w[CC * 16 * COUT];
    const int tid = threadIdx.x;
    const int b = blockIdx.y, oh0 = blockIdx.x * TOH;
    const int cibase = blockIdx.z * CLEN;
    const int cog = tid % NCOG, owg = tid / NCOG;
    const int co0 = TCO * cog, ow0 = owg * TOW;
    const int ihb = 2 * oh0 - 1;
    ull acc[NP][TOH][TOW];
#pragma unroll
    for (int p = 0; p < NP; p++)
#pragma unroll
        for (int o = 0; o < TOH; o++)
#pragma unroll
            for (int w = 0; w < TOW; w++) acc[p][o][w] = 0ull;

#pragma unroll 1
    for (int c0 = 0; c0 < CLEN; c0 += CC) {
        int ci0 = cibase + c0;
        __syncthreads();
        for (int i = tid; i < NROWS * CC * (HIN / 4); i += NTHR) {
            int r   = i / (CC * (HIN / 4));
            int rem = i - r * (CC * (HIN / 4));
            int cc  = rem / (HIN / 4);
            int x4  = rem - cc * (HIN / 4);
            int ih  = ihb + r;
            float4 v = make_float4(0.f, 0.f, 0.f, 0.f);
            if (ih >= 0 && ih < HIN)
                v = *reinterpret_cast<const float4*>(
                    &in[(((size_t)b * CIN + ci0 + cc) * HIN + ih) * HIN + 4 * x4]);
            *reinterpret_cast<float4*>(&s_in[(r * CC + cc) * HIN + 4 * x4]) = v;
        }
        const float4* wsrc = reinterpret_cast<const float4*>(wT + (size_t)ci0 * 16 * COUT);
        float4* wdst = reinterpret_cast<float4*>(s_w);
        for (int i = tid; i < CC * 16 * COUT / 4; i += NTHR) wdst[i] = wsrc[i];
        __syncthreads();
#pragma unroll 1
        for (int cc = 0; cc < CC; cc++) {
#pragma unroll
            for (int r = 0; r < NROWS; r++) {
                const float* row = &s_in[(r * CC + cc) * HIN];
                ull xd[2 * TOW + 2];
#pragma unroll
                for (int j = 0; j < 2 * TOW + 2; j++) {
                    int iw = 2 * ow0 - 1 + j;
                    float v = (iw >= 0 && iw < HIN) ? row[iw] : 0.f;
                    xd[j] = pk2(v);
                }
#pragma unroll
                for (int ot = 0; ot < TOH; ot++) {
                    int kh = r - 2 * ot;
                    if (kh >= 0 && kh < 4) {
                        ull wpk[NP][4];
#pragma unroll
                        for (int kw = 0; kw < 4; kw++) {
                            int idx = (cc * 16 + kh * 4 + kw) * COUT + co0;
                            if constexpr (NP == 2) {
                                ulonglong2 t = *reinterpret_cast<const ulonglong2*>(&s_w[idx]);
                                wpk[0][kw] = t.x; wpk[1][kw] = t.y;
                            } else {
                                wpk[0][kw] = *reinterpret_cast<const ull*>(&s_w[idx]);
                            }
                        }
#pragma unroll
                        for (int w = 0; w < TOW; w++)
#pragma unroll
                            for (int kw = 0; kw < 4; kw++)
#pragma unroll
                                for (int p = 0; p < NP; p++)
                                    fma2(acc[p][ot][w], xd[2 * w + kw], wpk[p][kw]);
                    }
                }
            }
        }
    }
    if constexpr (CSPLIT == 1) {
#pragma unroll
        for (int p = 0; p < NP; p++) {
            float bv0 = bias[co0 + 2 * p], bv1 = bias[co0 + 2 * p + 1];
#pragma unroll
            for (int ot = 0; ot < TOH; ot++)
#pragma unroll
                for (int w = 0; w < TOW; w++) {
                    float lo, hi; upk(acc[p][ot][w], lo, hi);
                    float v0 = fmaxf(lo + bv0, 0.f);
                    float v1 = fmaxf(hi + bv1, 0.f);
                    size_t o0 = (((size_t)b * COUT + co0 + 2 * p) * HO + oh0 + ot) * HO + ow0 + w;
                    out[o0] = v0;
                    out[o0 + (size_t)HO * HO] = v1;
                    if (out2) { out2[o0] = v0; out2[o0 + (size_t)HO * HO] = v1; }
                }
        }
    } else {
        float* dstp = out + (size_t)blockIdx.z * BB * COUT * HO * HO;
#pragma unroll
        for (int p = 0; p < NP; p++)
#pragma unroll
            for (int ot = 0; ot < TOH; ot++)
#pragma unroll
                for (int w = 0; w < TOW; w++) {
                    float lo, hi; upk(acc[p][ot][w], lo, hi);
                    size_t o0 = (((size_t)b * COUT + co0 + 2 * p) * HO + oh0 + ot) * HO + ow0 + w;
                    dstp[o0] = lo;
                    dstp[o0 + (size_t)HO * HO] = hi;
                }
    }
}

// ---------------- ds1 combine: 2 partials + bias + relu -> h2 ----------------
__global__ __launch_bounds__(256)
void k_comb1(const float* __restrict__ part, const float* __restrict__ bias,
             float* __restrict__ o) {
    int idx = blockIdx.x * 256 + threadIdx.x;   // over 64*64*1024
    int c = (idx >> 10) & 63;
    o[idx] = fmaxf(part[idx] + part[4194304 + idx] + bias[c], 0.f);
}

// ---------------- ds2 combine: 2 partials + bias + relu -> h3 ----------------
__global__ __launch_bounds__(256)
void k_comb2(const float* __restrict__ part, const float* __restrict__ bias,
             float* __restrict__ o) {
    int idx = blockIdx.x * 256 + threadIdx.x;   // over 64*128*256
    int c = (idx >> 8) & 127;
    o[idx] = fmaxf(part[idx] + part[2097152 + idx] + bias[c], 0.f);
}

// ---------------- ds3 combine: 4 partials + bias + relu -> g_h and d_out ----------------
__global__ __launch_bounds__(256)
void k_comb3(const float* __restrict__ part, const float* __restrict__ bias,
             float* __restrict__ hh, float* __restrict__ out) {
    int idx = blockIdx.x * 256 + threadIdx.x;   // over 64*128*64
    int c = (idx >> 6) & 127;
    float v = fmaxf(part[idx] + part[524288 + idx] + part[1048576 + idx]
                    + part[1572864 + idx] + bias[c], 0.f);
    hh[idx] = v;
    out[idx] = v;
}

// ---------------- res conv 3x3 p1 on 8x8: 2 co/thread, 32co blocks, zi=4 ----------------
__global__ __launch_bounds__(128)
void k_res(const float* __restrict__ in, const float* __restrict__ wT,
           float* __restrict__ part) {
    __shared__ float s_img[16 * 100];
    __shared__ float s_w[16 * 9 * 32];   // [ciL][k][32 co]
    const int tid = threadIdx.x;
    const int b = blockIdx.y;
    const int co_base = blockIdx.x * 32;
    const int zi = blockIdx.z;
    const int copl = tid & 15, ohp = tid >> 4;
    const int co0 = co_base + 2 * copl;
    ull acc[8];
#pragma unroll
    for (int w = 0; w < 8; w++) acc[w] = 0ull;

#pragma unroll 1
    for (int c2 = 0; c2 < 2; c2++) {
        int cib = zi * 32 + c2 * 16;
        __syncthreads();
        for (int i = tid; i < 16 * 36; i += 128) {
            int ci = i / 36, e = i - 36 * ci;
            int ofs;
            if (e < 10)      ofs = e;
            else if (e < 20) ofs = 90 + (e - 10);
            else { int r = ((e - 20) >> 1) + 1; int c = ((e - 20) & 1) * 9; ofs = r * 10 + c; }
            s_img[ci * 100 + ofs] = 0.f;
        }
        {
            int ci = tid >> 3, r = tid & 7;
            const float4* src = reinterpret_cast<const float4*>(
                in + (((size_t)(b * 128 + cib + ci)) * 8 + r) * 8);
            float4 v0 = src[0], v1 = src[1];
            float* d = &s_img[ci * 100 + (r + 1) * 10 + 1];
            d[0] = v0.x; d[1] = v0.y; d[2] = v0.z; d[3] = v0.w;
            d[4] = v1.x; d[5] = v1.y; d[6] = v1.z; d[7] = v1.w;
        }
        for (int i = tid; i < 16 * 9 * 8; i += 128) {
            int c8 = i & 7; int t = i >> 3; int k = t % 9; int ciL = t / 9;
            *reinterpret_cast<float4*>(&s_w[(ciL * 9 + k) * 32 + 4 * c8]) =
                *reinterpret_cast<const float4*>(
                    wT + ((size_t)(cib + ciL) * 9 + k) * 128 + co_base + 4 * c8);
        }
        __syncthreads();
#pragma unroll 1
        for (int ciL = 0; ciL < 16; ciL++) {
            ull wp[9];
#pragma unroll
            for (int k = 0; k < 9; k++)
                wp[k] = *reinterpret_cast<const ull*>(&s_w[(ciL * 9 + k) * 32 + 2 * copl]);
#pragma unroll
            for (int kh = 0; kh < 3; kh++) {
                const float* row = &s_img[ciL * 100 + (ohp + kh) * 10];
                ull xd[10];
#pragma unroll
                for (int j = 0; j < 10; j++) xd[j] = pk2(row[j]);
#pragma unroll
                for (int ow = 0; ow < 8; ow++)
#pragma unroll
                    for (int kw = 0; kw < 3; kw++)
                        fma2(acc[ow], xd[ow + kw], wp[kh * 3 + kw]);
            }
        }
    }
    float* dst = part + (size_t)zi * 524288 + ((size_t)(b * 128 + co0)) * 64 + ohp * 8;
#pragma unroll
    for (int ow = 0; ow < 8; ow++) {
        float lo, hi; upk(acc[ow], lo, hi);
        dst[ow] = lo; dst[64 + ow] = hi;
    }
}

// ---------------- stage A: combine 4 partials, per-(channel,slice) stats ----------------
__global__ __launch_bounds__(256)
void k_pstats(const float* __restrict__ part) {
    int c = blockIdx.x, s = blockIdx.y, tid = threadIdx.x;
    float sum = 0.f, sq = 0.f;
#pragma unroll
    for (int t = 0; t < 2; t++) {
        int i = s * 512 + t * 256 + tid;       // i = b*64 + p
        int b = i >> 6, p = i & 63;
        size_t idx = ((size_t)(b * 128 + c)) * 64 + p;
        float v = part[idx] + part[524288 + idx] + part[1048576 + idx] + part[1572864 + idx];
        g_comb[idx] = v;
        sum += v; sq += v * v;
    }
    __shared__ float rs[256], rs2[256];
    rs[tid] = sum; rs2[tid] = sq;
    __syncthreads();
    for (int o = 128; o > 0; o >>= 1) {
        if (tid < o) { rs[tid] += rs[tid + o]; rs2[tid] += rs2[tid + o]; }
        __syncthreads();
    }
    if (tid == 0) g_psum[c * 8 + s] = make_float2(rs[0], rs2[0]);
}

// ---------------- stage B: fold psum -> scale/shift, normalize + relu ----------------
__global__ __launch_bounds__(256)
void k_norm(const float* __restrict__ gamma, const float* __restrict__ beta,
            float* __restrict__ o1) {
    int idx = blockIdx.x * 256 + threadIdx.x;
    int c = (idx >> 6) & 127;
    float s = 0.f, s2 = 0.f;
#pragma unroll
    for (int q = 0; q < 8; q++) {
        float2 v = g_psum[c * 8 + q];
        s += v.x; s2 += v.y;
    }
    float mean = s / 4096.f;
    float var  = s2 / 4096.f - mean * mean;
    float sc   = gamma[c] * rsqrtf(var + 1e-5f);
    float sh   = beta[c] - mean * sc;
    o1[idx] = fmaxf(fmaf(sc, g_comb[idx], sh), 0.f);
}

// ---------------- stage B': fold psum, normalize + residual + relu; g_h, map_skip ----------------
__global__ __launch_bounds__(256)
void k_applyres(const float* __restrict__ gamma, const float* __restrict__ beta,
                float* __restrict__ dskip) {
    int idx = blockIdx.x * 256 + threadIdx.x;
    int c = (idx >> 6) & 127;
    float s = 0.f, s2 = 0.f;
#pragma unroll
    for (int q = 0; q < 8; q++) {
        float2 v = g_psum[c * 8 + q];
        s += v.x; s2 += v.y;
    }
    float mean = s / 4096.f;
    float var  = s2 / 4096.f - mean * mean;
    float sc   = gamma[c] * rsqrtf(var + 1e-5f);
    float sh   = beta[c] - mean * sc;
    float h = fmaxf(fmaf(sc, g_comb[idx], sh) + g_h[idx], 0.f);
    g_h[idx] = h;
    dskip[idx] += h;
}

// ---------------- fc: 4 b rows in dynamic smem, 32 j per block ----------------
__global__ __launch_bounds__(256)
void k_fc(const float* __restrict__ w, const float* __restrict__ bias,
          float* __restrict__ outp) {
    extern __shared__ float s_a[];   // 4 * 8192
    int b0 = blockIdx.y * 4;
    int tid = threadIdx.x;
    float4* sd = reinterpret_cast<float4*>(s_a);
    const float4* src = reinterpret_cast<const float4*>(g_h + (size_t)b0 * 8192);
    for (int i = tid; i < 8192; i += 256) sd[i] = src[i];
    __syncthreads();
    int wrp = tid >> 5, lane = tid & 31;
#pragma unroll 1
    for (int q = 0; q < 4; q++) {
        int j = blockIdx.x * 32 + wrp * 4 + q;
        const float4* wr = reinterpret_cast<const float4*>(w + (size_t)j * 8192);
        float acc[4];
#pragma unroll
        for (int bl = 0; bl < 4; bl++) acc[bl] = 0.f;
#pragma unroll 2
        for (int i = lane; i < 2048; i += 32) {
            float4 wv = wr[i];
#pragma unroll
            for (int bl = 0; bl < 4; bl++) {
                float4 av = sd[bl * 2048 + i];
                acc[bl] += wv.x * av.x + wv.y * av.y + wv.z * av.z + wv.w * av.w;
            }
        }
#pragma unroll
        for (int o = 16; o > 0; o >>= 1)
#pragma unroll
            for (int bl = 0; bl < 4; bl++)
                acc[bl] += __shfl_down_sync(0xffffffffu, acc[bl], o);
        if (lane == 0) {
            float bv = bias[j];
#pragma unroll
            for (int bl = 0; bl < 4; bl++)
                outp[(size_t)(b0 + bl) * 256 + j] = fmaxf(acc[bl] + bv, 0.f);
        }
    }
}

// ---------------- launch ----------------
extern "C" void kernel_launch(void* const* d_in, const int* in_sizes, int n_in,
                              void* d_out, int out_size) {
    const float* x    = (const float*)d_in[0];
    const float* emb  = (const float*)d_in[1];
    const int*   xy   = (const int*)  d_in[2];
    const float* c1w  = (const float*)d_in[3];
    const float* pw   = (const float*)d_in[4];
    const float* pb   = (const float*)d_in[5];
    const float* ds1w = (const float*)d_in[6];
    const float* ds1b = (const float*)d_in[7];
    const float* ds2w = (const float*)d_in[8];
    const float* ds2b = (const float*)d_in[9];
    const float* ds3w = (const float*)d_in[10];
    const float* ds3b = (const float*)d_in[11];
    const float* rc1w = (const float*)d_in[12];
    const float* bn1g = (const float*)d_in[13];
    const float* bn1b = (const float*)d_in[14];
    const float* rc2w = (const float*)d_in[15];
    const float* bn2g = (const float*)d_in[16];
    const float* bn2b = (const float*)d_in[17];
    const float* fcw  = (const float*)d_in[18];
    const float* fcb  = (const float*)d_in[19];
    float* out = (float*)d_out;

    float *scat, *h1, *h2, *h3, *hh, *pA, *pB, *pd1, *pd2, *pd3, *wt1, *wt2, *wt3, *rwt;
    cudaGetSymbolAddress((void**)&scat, g_scat);
    cudaGetSymbolAddress((void**)&h1,   g_h1);
    cudaGetSymbolAddress((void**)&h2,   g_h2);
    cudaGetSymbolAddress((void**)&h3,   g_h3);
    cudaGetSymbolAddress((void**)&hh,   g_h);
    cudaGetSymbolAddress((void**)&pA,   g_partA);
    cudaGetSymbolAddress((void**)&pB,   g_partB);
    cudaGetSymbolAddress((void**)&pd1,  g_pd1);
    cudaGetSymbolAddress((void**)&pd2,  g_pd2);
    cudaGetSymbolAddress((void**)&pd3,  g_pd3);
    cudaGetSymbolAddress((void**)&wt1,  g_wt1);
    cudaGetSymbolAddress((void**)&wt2,  g_wt2);
    cudaGetSymbolAddress((void**)&wt3,  g_wt3);
    cudaGetSymbolAddress((void**)&rwt,  g_rwt);

    cudaFuncSetAttribute((const void*)k_fc, cudaFuncAttributeMaxDynamicSharedMemorySize, 131072);

    // order chosen so launch #4 (profiled slot) = ds1
    k_tr_ds<32, 64><<<(32 * 16 * 64 + 255) / 256, 256>>>(ds1w, wt1);          // 1
    k_scatter<<<(BB * NENT) / 8, 256>>>(emb, xy, c1w);                        // 2 (g_scat pre-zeroed)
    k_proj<<<1024, 256>>>(x, pw, pb);                                         // 3
    // ds1: ci-split x2 -> 2048 blocks (kills 2-wave tail), combine after
    k_down<32, 64, 64, 4, 4, 2, 4, 128, 2><<<dim3(16, BB, 2), 128>>>(h1, wt1, nullptr, pd1, nullptr); // 4 <- profiled
    k_comb1<<<16384, 256>>>(pd1, ds1b, h2);

    k_tr_ds<64, 128> <<<(64 * 16 * 128 + 255) / 256, 256>>>(ds2w, wt2);
    k_tr_ds<128, 128><<<(128 * 16 * 128 + 255) / 256, 256>>>(ds3w, wt3);
    k_tr_res<<<(2 * 589824 + 255) / 256, 256>>>(rc1w, rc2w);

    // ds2: ci-split x2 -> 1024 blocks, combine
    k_down<64, 32, 128, 4, 4, 2, 4, 128, 2><<<dim3(8, BB, 2), 128>>>(h2, wt2, nullptr, pd2, nullptr);
    k_comb2<<<8192, 256>>>(pd2, ds2b, h3);
    // ds3: ci-split x4 -> 1024 blocks, combine (writes g_h and map_skip init)
    k_down<128, 16, 128, 2, 4, 2, 4, 128, 4><<<dim3(4, BB, 4), 128>>>(h3, wt3, nullptr, pd3, nullptr);
    k_comb3<<<2048, 256>>>(pd3, ds3b, hh, out);

    for (int i = 0; i < 4; i++) {
        k_res<<<dim3(4, BB, 4), 128>>>(hh, rwt + (size_t)i * 147456, pA);
        k_pstats<<<dim3(128, 8), 256>>>(pA);
        k_norm<<<2048, 256>>>(bn1g + i * 128, bn1b + i * 128, h3);   // h3 reused as o1
        k_res<<<dim3(4, BB, 4), 128>>>(h3, rwt + (size_t)(4 + i) * 147456, pB);
        k_pstats<<<dim3(128, 8), 256>>>(pB);
        k_applyres<<<2048, 256>>>(bn2g + i * 128, bn2b + i * 128, out);
    }

    k_fc<<<dim3(8, 16), 256, 131072>>>(fcw, fcb, out + (size_t)BB * 128 * 64);

    // re-zero scatter buffer for the next invocation (replay-safe)
    k_zero4<<<8192, 256>>>(reinterpret_cast<float4*>(scat));
}

// round 14
// speedup vs baseline: 1.1363x; 1.0020x over previous
#include <cuda_runtime.h>
#include <cuda_bf16.h>

typedef unsigned long long ull;
#define BB 64
#define NENT 512

// ---------------- device scratch ----------------
__device__ float g_scat[BB*32*4096];   // zero-initialized at load; re-zeroed at end of each launch
__device__ float g_h1[BB*32*4096];
__device__ float g_h2[BB*64*1024];
__device__ float g_h3[BB*128*256];     // also reused as normalized o1 in res blocks
__device__ float g_h [BB*128*64];
__device__ float g_comb[BB*128*64];
__device__ float2 g_psum[128*8];
__device__ float g_partA[4*BB*128*64];
__device__ float g_partB[4*BB*128*64];
__device__ float g_pd2[2*BB*128*256];
__device__ float g_pd3[4*BB*128*64];
__device__ float g_wt1[32*16*64];
__device__ float g_wt2[64*16*128];
__device__ float g_wt3[128*16*128];
__device__ float g_rwt[8*128*9*128];

// ---------------- f32x2 helpers (bit-exact fp32 pairs) ----------------
__device__ __forceinline__ ull pk2(float v) {
    ull r; asm("mov.b64 %0, {%1,%2};" : "=l"(r) : "f"(v), "f"(v)); return r;
}
__device__ __forceinline__ void fma2(ull& d, ull a, ull b) {
    asm("fma.rn.f32x2 %0, %1, %2, %0;" : "+l"(d) : "l"(a), "l"(b));
}
__device__ __forceinline__ void upk(ull v, float& lo, float& hi) {
    asm("mov.b64 {%0,%1}, %2;" : "=f"(lo), "=f"(hi) : "l"(v));
}

// ---------------- small utility kernels ----------------
__global__ void k_zero4(float4* p) {
    p[blockIdx.x * 256 + threadIdx.x] = make_float4(0.f, 0.f, 0.f, 0.f);
}

// [co][ci][k16] -> [ci][k16][co]
template<int CIN, int COUT>
__global__ void k_tr_ds(const float* __restrict__ w, float* __restrict__ o) {
    int idx = blockIdx.x * 256 + threadIdx.x;
    if (idx >= CIN * 16 * COUT) return;
    int co = idx % COUT; int t = idx / COUT; int k = t % 16; int ci = t / 16;
    o[idx] = w[(co * CIN + ci) * 16 + k];
}

// res weights: [i][co][ci][k9] -> g_rwt[i'][(ci*9+k)*128+co]
__global__ void k_tr_res(const float* __restrict__ w1, const float* __restrict__ w2) {
    int idx = blockIdx.x * 256 + threadIdx.x;
    const int half = 589824;
    if (idx >= 2 * half) return;
    const float* s = (idx < half) ? w1 : w2;
    int id = (idx < half) ? idx : idx - half;
    int co = id & 127; int t = id >> 7; int k = t % 9; int t2 = t / 9;
    int ci = t2 & 127; int i = t2 >> 7;
    int dsti = (idx < half) ? i : (4 + i);
    g_rwt[(size_t)dsti * 147456 + (ci * 9 + k) * 128 + co] =
        s[(((size_t)i * 128 + co) * 128 + ci) * 9 + k];
}

// ---------------- scatter: warp per 8 entities (g_scat pre-zeroed) ----------------
__global__ __launch_bounds__(256)
void k_scatter(const float* __restrict__ emb, const int* __restrict__ xy,
               const float* __restrict__ w1) {
    __shared__ float s_wT[256 * 33];
    int tid = threadIdx.x;
    for (int i = tid; i < 32 * 256; i += blockDim.x) {
        int c = i >> 8, d = i & 255;
        s_wT[d * 33 + c] = w1[i];
    }
    __syncthreads();
    int warp0 = blockIdx.x * 8 + (tid >> 5);   // 512 blocks x 8 warps
    int lane = tid & 31;
#pragma unroll 1
    for (int e = 0; e < 8; e++) {
        int ent = warp0 * 8 + e;
        int b = ent / NENT, n = ent - b * NENT;
        const int* bits = xy + (size_t)(b * NENT + n) * 16;
        if (bits[0] == -1000000000) continue;
        int bit = (lane < 16) ? bits[lane] : 0;
        int contrib;
        if (lane < 8)       contrib = bit << (7 - lane);
        else if (lane < 16) contrib = bit << (31 - lane);
        else                contrib = 0;
        int pack = __reduce_add_sync(0xffffffffu, contrib);
        int xv = (pack & 0xffff) >> 2;
        int yv = (pack >> 16) >> 2;
        const float4* e4 = reinterpret_cast<const float4*>(emb + (size_t)(b * NENT + n) * 256);
        float acc = 0.f;
#pragma unroll 8
        for (int i = 0; i < 64; i++) {
            float4 v = e4[i];
            acc += v.x * s_wT[(4 * i + 0) * 33 + lane];
            acc += v.y * s_wT[(4 * i + 1) * 33 + lane];
            acc += v.z * s_wT[(4 * i + 2) * 33 + lane];
            acc += v.w * s_wT[(4 * i + 3) * 33 + lane];
        }
        acc = fmaxf(acc, 0.f);
        if (acc != 0.f)
            atomicAdd(&g_scat[((size_t)b * 32 + lane) * 4096 + yv * 64 + xv], acc);
    }
}

// ---------------- project 1x1: thread=pixel, all 32 co, f32x2 ----------------
__global__ __launch_bounds__(256)
void k_proj(const float* __restrict__ x, const float* __restrict__ pw,
            const float* __restrict__ pb) {
    __shared__ float s_w[50 * 32];   // [ci][co]
    __shared__ float s_b[32];
    int tid = threadIdx.x;
    for (int i = tid; i < 1600; i += 256) {
        int ci = i >> 5, co = i & 31;
        s_w[i] = pw[co * 50 + ci];
    }
    if (tid < 32) s_b[tid] = pb[tid];
    __syncthreads();
    int b = blockIdx.x >> 4;
    int p = ((blockIdx.x & 15) << 8) + tid;
    ull acc[16];
#pragma unroll
    for (int g = 0; g < 16; g++) acc[g] = 0ull;
    const float* srcs = g_scat + (size_t)b * 32 * 4096 + p;
#pragma unroll 1
    for (int ci = 0; ci < 32; ci++) {
        ull vp = pk2(srcs[ci * 4096]);
        const ulonglong2* wrow = reinterpret_cast<const ulonglong2*>(&s_w[ci * 32]);
#pragma unroll
        for (int gg = 0; gg < 8; gg++) {
            ulonglong2 w2 = wrow[gg];
            fma2(acc[2 * gg], vp, w2.x);
            fma2(acc[2 * gg + 1], vp, w2.y);
        }
    }
    const float* srcx = x + (size_t)b * 18 * 4096 + p;
#pragma unroll 1
    for (int cx = 0; cx < 18; cx++) {
        ull vp = pk2(srcx[cx * 4096]);
        const ulonglong2* wrow = reinterpret_cast<const ulonglong2*>(&s_w[(32 + cx) * 32]);
#pragma unroll
        for (int gg = 0; gg < 8; gg++) {
            ulonglong2 w2 = wrow[gg];
            fma2(acc[2 * gg], vp, w2.x);
            fma2(acc[2 * gg + 1], vp, w2.y);
        }
    }
    float* dst = g_h1 + (size_t)b * 32 * 4096 + p;
#pragma unroll
    for (int g = 0; g < 16; g++) {
        float lo, hi; upk(acc[g], lo, hi);
        dst[(2 * g) * 4096]     = fmaxf(lo + s_b[2 * g], 0.f);
        dst[(2 * g + 1) * 4096] = fmaxf(hi + s_b[2 * g + 1], 0.f);
    }
}

// ---------------- down conv k=4 s=2 p=1, f32x2; CSPLIT>1 -> raw partials ----------------
template<int CIN, int HIN, int COUT, int TCO, int TOW, int TOH, int CC, int NTHR, int CSPLIT>
__global__ __launch_bounds__(NTHR)
void k_down(const float* __restrict__ in, const float* __restrict__ wT,
            const float* __restrict__ bias, float* __restrict__ out,
            float* __restrict__ out2) {
    constexpr int HO    = HIN / 2;
    constexpr int NCOG  = COUT / TCO;
    constexpr int NROWS = 2 * TOH + 2;
    constexpr int NP    = TCO / 2;
    constexpr int CLEN  = CIN / CSPLIT;
    static_assert(NTHR == NCOG * (HO / TOW), "thread count");
    __shared__ float s_in[NROWS * CC * HIN];
    __shared__ float s_w[CC * 16 * COUT];
    const int tid = threadIdx.x;
    const int b = blockIdx.y, oh0 = blockIdx.x * TOH;
    const int cibase = blockIdx.z * CLEN;
    const int cog = tid % NCOG, owg = tid / NCOG;
    const int co0 = TCO * cog, ow0 = owg * TOW;
    const int ihb = 2 * oh0 - 1;
    ull acc[NP][TOH][TOW];
#pragma unroll
    for (int p = 0; p < NP; p++)
#pragma unroll
        for (int o = 0; o < TOH; o++)
#pragma unroll
            for (int w = 0; w < TOW; w++) acc[p][o][w] = 0ull;

#pragma unroll 1
    for (int c0 = 0; c0 < CLEN; c0 += CC) {
        int ci0 = cibase + c0;
        __syncthreads();
        for (int i = tid; i < NROWS * CC * (HIN / 4); i += NTHR) {
            int r   = i / (CC * (HIN / 4));
            int rem = i - r * (CC * (HIN / 4));
            int cc  = rem / (HIN / 4);
            int x4  = rem - cc * (HIN / 4);
            int ih  = ihb + r;
            float4 v = make_float4(0.f, 0.f, 0.f, 0.f);
            if (ih >= 0 && ih < HIN)
                v = *reinterpret_cast<const float4*>(
                    &in[(((size_t)b * CIN + ci0 + cc) * HIN + ih) * HIN + 4 * x4]);
            *reinterpret_cast<float4*>(&s_in[(r * CC + cc) * HIN + 4 * x4]) = v;
        }
        const float4* wsrc = reinterpret_cast<const float4*>(wT + (size_t)ci0 * 16 * COUT);
        float4* wdst = reinterpret_cast<float4*>(s_w);
        for (int i = tid; i < CC * 16 * COUT / 4; i += NTHR) wdst[i] = wsrc[i];
        __syncthreads();
#pragma unroll 1
        for (int cc = 0; cc < CC; cc++) {
#pragma unroll
            for (int r = 0; r < NROWS; r++) {
                const float* row = &s_in[(r * CC + cc) * HIN];
                ull xd[2 * TOW + 2];
#pragma unroll
                for (int j = 0; j < 2 * TOW + 2; j++) {
                    int iw = 2 * ow0 - 1 + j;
                    float v = (iw >= 0 && iw < HIN) ? row[iw] : 0.f;
                    xd[j] = pk2(v);
                }
#pragma unroll
                for (int ot = 0; ot < TOH; ot++) {
                    int kh = r - 2 * ot;
                    if (kh >= 0 && kh < 4) {
                        ull wpk[NP][4];
#pragma unroll
                        for (int kw = 0; kw < 4; kw++) {
                            int idx = (cc * 16 + kh * 4 + kw) * COUT + co0;
                            if constexpr (NP == 2) {
                                ulonglong2 t = *reinterpret_cast<const ulonglong2*>(&s_w[idx]);
                                wpk[0][kw] = t.x; wpk[1][kw] = t.y;
                            } else {
                                wpk[0][kw] = *reinterpret_cast<const ull*>(&s_w[idx]);
                            }
                        }
#pragma unroll
                        for (int w = 0; w < TOW; w++)
#pragma unroll
                            for (int kw = 0; kw < 4; kw++)
#pragma unroll
                                for (int p = 0; p < NP; p++)
                                    fma2(acc[p][ot][w], xd[2 * w + kw], wpk[p][kw]);
                    }
                }
            }
        }
    }
    if constexpr (CSPLIT == 1) {
#pragma unroll
        for (int p = 0; p < NP; p++) {
            float bv0 = bias[co0 + 2 * p], bv1 = bias[co0 + 2 * p + 1];
#pragma unroll
            for (int ot = 0; ot < TOH; ot++)
#pragma unroll
                for (int w = 0; w < TOW; w++) {
                    float lo, hi; upk(acc[p][ot][w], lo, hi);
                    float v0 = fmaxf(lo + bv0, 0.f);
                    float v1 = fmaxf(hi + bv1, 0.f);
                    size_t o0 = (((size_t)b * COUT + co0 + 2 * p) * HO + oh0 + ot) * HO + ow0 + w;
                    out[o0] = v0;
                    out[o0 + (size_t)HO * HO] = v1;
                    if (out2) { out2[o0] = v0; out2[o0 + (size_t)HO * HO] = v1; }
                }
        }
    } else {
        float* dstp = out + (size_t)blockIdx.z * BB * COUT * HO * HO;
#pragma unroll
        for (int p = 0; p < NP; p++)
#pragma unroll
            for (int ot = 0; ot < TOH; ot++)
#pragma unroll
                for (int w = 0; w < TOW; w++) {
                    float lo, hi; upk(acc[p][ot][w], lo, hi);
                    size_t o0 = (((size_t)b * COUT + co0 + 2 * p) * HO + oh0 + ot) * HO + ow0 + w;
                    dstp[o0] = lo;
                    dstp[o0 + (size_t)HO * HO] = hi;
                }
    }
}

// ---------------- ds2 combine: 2 partials + bias + relu -> h3 ----------------
__global__ __launch_bounds__(256)
void k_comb2(const float* __restrict__ part, const float* __restrict__ bias,
             float* __restrict__ o) {
    int idx = blockIdx.x * 256 + threadIdx.x;   // over 64*128*256
    int c = (idx >> 8) & 127;
    o[idx] = fmaxf(part[idx] + part[2097152 + idx] + bias[c], 0.f);
}

// ---------------- ds3 combine: 4 partials + bias + relu -> g_h and d_out ----------------
__global__ __launch_bounds__(256)
void k_comb3(const float* __restrict__ part, const float* __restrict__ bias,
             float* __restrict__ hh, float* __restrict__ out) {
    int idx = blockIdx.x * 256 + threadIdx.x;   // over 64*128*64
    int c = (idx >> 6) & 127;
    float v = fmaxf(part[idx] + part[524288 + idx] + part[1048576 + idx]
                    + part[1572864 + idx] + bias[c], 0.f);
    hh[idx] = v;
    out[idx] = v;
}

// ---------------- res conv 3x3 p1 on 8x8: 2 co/thread, 32co blocks, zi=4 ----------------
__global__ __launch_bounds__(128)
void k_res(const float* __restrict__ in, const float* __restrict__ wT,
           float* __restrict__ part) {
    __shared__ float s_img[16 * 100];
    __shared__ float s_w[16 * 9 * 32];   // [ciL][k][32 co]
    const int tid = threadIdx.x;
    const int b = blockIdx.y;
    const int co_base = blockIdx.x * 32;
    const int zi = blockIdx.z;
    const int copl = tid & 15, ohp = tid >> 4;
    const int co0 = co_base + 2 * copl;
    ull acc[8];
#pragma unroll
    for (int w = 0; w < 8; w++) acc[w] = 0ull;

#pragma unroll 1
    for (int c2 = 0; c2 < 2; c2++) {
        int cib = zi * 32 + c2 * 16;
        __syncthreads();
        for (int i = tid; i < 16 * 36; i += 128) {
            int ci = i / 36, e = i - 36 * ci;
            int ofs;
            if (e < 10)      ofs = e;
            else if (e < 20) ofs = 90 + (e - 10);
            else { int r = ((e - 20) >> 1) + 1; int c = ((e - 20) & 1) * 9; ofs = r * 10 + c; }
            s_img[ci * 100 + ofs] = 0.f;
        }
        {
            int ci = tid >> 3, r = tid & 7;
            const float4* src = reinterpret_cast<const float4*>(
                in + (((size_t)(b * 128 + cib + ci)) * 8 + r) * 8);
            float4 v0 = src[0], v1 = src[1];
            float* d = &s_img[ci * 100 + (r + 1) * 10 + 1];
            d[0] = v0.x; d[1] = v0.y; d[2] = v0.z; d[3] = v0.w;
            d[4] = v1.x; d[5] = v1.y; d[6] = v1.z; d[7] = v1.w;
        }
        for (int i = tid; i < 16 * 9 * 8; i += 128) {
            int c8 = i & 7; int t = i >> 3; int k = t % 9; int ciL = t / 9;
            *reinterpret_cast<float4*>(&s_w[(ciL * 9 + k) * 32 + 4 * c8]) =
                *reinterpret_cast<const float4*>(
                    wT + ((size_t)(cib + ciL) * 9 + k) * 128 + co_base + 4 * c8);
        }
        __syncthreads();
#pragma unroll 1
        for (int ciL = 0; ciL < 16; ciL++) {
            ull wp[9];
#pragma unroll
            for (int k = 0; k < 9; k++)
                wp[k] = *reinterpret_cast<const ull*>(&s_w[(ciL * 9 + k) * 32 + 2 * copl]);
#pragma unroll
            for (int kh = 0; kh < 3; kh++) {
                const float* row = &s_img[ciL * 100 + (ohp + kh) * 10];
                ull xd[10];
#pragma unroll
                for (int j = 0; j < 10; j++) xd[j] = pk2(row[j]);
#pragma unroll
                for (int ow = 0; ow < 8; ow++)
#pragma unroll
                    for (int kw = 0; kw < 3; kw++)
                        fma2(acc[ow], xd[ow + kw], wp[kh * 3 + kw]);
            }
        }
    }
    float* dst = part + (size_t)zi * 524288 + ((size_t)(b * 128 + co0)) * 64 + ohp * 8;
#pragma unroll
    for (int ow = 0; ow < 8; ow++) {
        float lo, hi; upk(acc[ow], lo, hi);
        dst[ow] = lo; dst[64 + ow] = hi;
    }
}

// ---------------- stage A: combine 4 partials, per-(channel,slice) stats ----------------
__global__ __launch_bounds__(256)
void k_pstats(const float* __restrict__ part) {
    int c = blockIdx.x, s = blockIdx.y, tid = threadIdx.x;
    float sum = 0.f, sq = 0.f;
#pragma unroll
    for (int t = 0; t < 2; t++) {
        int i = s * 512 + t * 256 + tid;       // i = b*64 + p
        int b = i >> 6, p = i & 63;
        size_t idx = ((size_t)(b * 128 + c)) * 64 + p;
        float v = part[idx] + part[524288 + idx] + part[1048576 + idx] + part[1572864 + idx];
        g_comb[idx] = v;
        sum += v; sq += v * v;
    }
    __shared__ float rs[256], rs2[256];
    rs[tid] = sum; rs2[tid] = sq;
    __syncthreads();
    for (int o = 128; o > 0; o >>= 1) {
        if (tid < o) { rs[tid] += rs[tid + o]; rs2[tid] += rs2[tid + o]; }
        __syncthreads();
    }
    if (tid == 0) g_psum[c * 8 + s] = make_float2(rs[0], rs2[0]);
}

// ---------------- stage B: fold psum -> scale/shift, normalize + relu ----------------
__global__ __launch_bounds__(256)
void k_norm(const float* __restrict__ gamma, const float* __restrict__ beta,
            float* __restrict__ o1) {
    int idx = blockIdx.x * 256 + threadIdx.x;
    int c = (idx >> 6) & 127;
    float s = 0.f, s2 = 0.f;
#pragma unroll
    for (int q = 0; q < 8; q++) {
        float2 v = g_psum[c * 8 + q];
        s += v.x; s2 += v.y;
    }
    float mean = s / 4096.f;
    float var  = s2 / 4096.f - mean * mean;
    float sc   = gamma[c] * rsqrtf(var + 1e-5f);
    float sh   = beta[c] - mean * sc;
    o1[idx] = fmaxf(fmaf(sc, g_comb[idx], sh), 0.f);
}

// ---------------- stage B': fold psum, normalize + residual + relu; g_h, map_skip ----------------
__global__ __launch_bounds__(256)
void k_applyres(const float* __restrict__ gamma, const float* __restrict__ beta,
                float* __restrict__ dskip) {
    int idx = blockIdx.x * 256 + threadIdx.x;
    int c = (idx >> 6) & 127;
    float s = 0.f, s2 = 0.f;
#pragma unroll
    for (int q = 0; q < 8; q++) {
        float2 v = g_psum[c * 8 + q];
        s += v.x; s2 += v.y;
    }
    float mean = s / 4096.f;
    float var  = s2 / 4096.f - mean * mean;
    float sc   = gamma[c] * rsqrtf(var + 1e-5f);
    float sh   = beta[c] - mean * sc;
    float h = fmaxf(fmaf(sc, g_comb[idx], sh) + g_h[idx], 0.f);
    g_h[idx] = h;
    dskip[idx] += h;
}

// ---------------- fc: 4 b rows in dynamic smem, 32 j per block ----------------
__global__ __launch_bounds__(256)
void k_fc(const float* __restrict__ w, const float* __restrict__ bias,
          float* __restrict__ outp) {
    extern __shared__ float s_a[];   // 4 * 8192
    int b0 = blockIdx.y * 4;
    int tid = threadIdx.x;
    float4* sd = reinterpret_cast<float4*>(s_a);
    const float4* src = reinterpret_cast<const float4*>(g_h + (size_t)b0 * 8192);
    for (int i = tid; i < 8192; i += 256) sd[i] = src[i];
    __syncthreads();
    int wrp = tid >> 5, lane = tid & 31;
#pragma unroll 1
    for (int q = 0; q < 4; q++) {
        int j = blockIdx.x * 32 + wrp * 4 + q;
        const float4* wr = reinterpret_cast<const float4*>(w + (size_t)j * 8192);
        float acc[4];
#pragma unroll
        for (int bl = 0; bl < 4; bl++) acc[bl] = 0.f;
#pragma unroll 2
        for (int i = lane; i < 2048; i += 32) {
            float4 wv = wr[i];
#pragma unroll
            for (int bl = 0; bl < 4; bl++) {
                float4 av = sd[bl * 2048 + i];
                acc[bl] += wv.x * av.x + wv.y * av.y + wv.z * av.z + wv.w * av.w;
            }
        }
#pragma unroll
        for (int o = 16; o > 0; o >>= 1)
#pragma unroll
            for (int bl = 0; bl < 4; bl++)
                acc[bl] += __shfl_down_sync(0xffffffffu, acc[bl], o);
        if (lane == 0) {
            float bv = bias[j];
#pragma unroll
            for (int bl = 0; bl < 4; bl++)
                outp[(size_t)(b0 + bl) * 256 + j] = fmaxf(acc[bl] + bv, 0.f);
        }
    }
}

// ---------------- launch ----------------
extern "C" void kernel_launch(void* const* d_in, const int* in_sizes, int n_in,
                              void* d_out, int out_size) {
    const float* x    = (const float*)d_in[0];
    const float* emb  = (const float*)d_in[1];
    const int*   xy   = (const int*)  d_in[2];
    const float* c1w  = (const float*)d_in[3];
    const float* pw   = (const float*)d_in[4];
    const float* pb   = (const float*)d_in[5];
    const float* ds1w = (const float*)d_in[6];
    const float* ds1b = (const float*)d_in[7];
    const float* ds2w = (const float*)d_in[8];
    const float* ds2b = (const float*)d_in[9];
    const float* ds3w = (const float*)d_in[10];
    const float* ds3b = (const float*)d_in[11];
    const float* rc1w = (const float*)d_in[12];
    const float* bn1g = (const float*)d_in[13];
    const float* bn1b = (const float*)d_in[14];
    const float* rc2w = (const float*)d_in[15];
    const float* bn2g = (const float*)d_in[16];
    const float* bn2b = (const float*)d_in[17];
    const float* fcw  = (const float*)d_in[18];
    const float* fcb  = (const float*)d_in[19];
    float* out = (float*)d_out;

    float *scat, *h1, *h2, *h3, *hh, *pA, *pB, *pd2, *pd3, *wt1, *wt2, *wt3, *rwt;
    cudaGetSymbolAddress((void**)&scat, g_scat);
    cudaGetSymbolAddress((void**)&h1,   g_h1);
    cudaGetSymbolAddress((void**)&h2,   g_h2);
    cudaGetSymbolAddress((void**)&h3,   g_h3);
    cudaGetSymbolAddress((void**)&hh,   g_h);
    cudaGetSymbolAddress((void**)&pA,   g_partA);
    cudaGetSymbolAddress((void**)&pB,   g_partB);
    cudaGetSymbolAddress((void**)&pd2,  g_pd2);
    cudaGetSymbolAddress((void**)&pd3,  g_pd3);
    cudaGetSymbolAddress((void**)&wt1,  g_wt1);
    cudaGetSymbolAddress((void**)&wt2,  g_wt2);
    cudaGetSymbolAddress((void**)&wt3,  g_wt3);
    cudaGetSymbolAddress((void**)&rwt,  g_rwt);

    cudaFuncSetAttribute((const void*)k_fc, cudaFuncAttributeMaxDynamicSharedMemorySize, 131072);

    // order chosen so launch #4 (profiled slot) = ds1
    k_tr_ds<32, 64><<<(32 * 16 * 64 + 255) / 256, 256>>>(ds1w, wt1);          // 1
    k_scatter<<<512, 256>>>(emb, xy, c1w);                                    // 2 (g_scat pre-zeroed)
    k_proj<<<1024, 256>>>(x, pw, pb);                                         // 3
    // ds1: converged R11 config — CSPLIT=1, direct epilogue
    k_down<32, 64, 64, 4, 4, 2, 4, 128, 1><<<dim3(16, BB), 128>>>(h1, wt1, ds1b, h2, nullptr); // 4 <- profiled

    k_tr_ds<64, 128> <<<(64 * 16 * 128 + 255) / 256, 256>>>(ds2w, wt2);
    k_tr_ds<128, 128><<<(128 * 16 * 128 + 255) / 256, 256>>>(ds3w, wt3);
    k_tr_res<<<(2 * 589824 + 255) / 256, 256>>>(rc1w, rc2w);

    // ds2: ci-split x2 -> 1024 blocks, combine
    k_down<64, 32, 128, 4, 4, 2, 4, 128, 2><<<dim3(8, BB, 2), 128>>>(h2, wt2, nullptr, pd2, nullptr);
    k_comb2<<<8192, 256>>>(pd2, ds2b, h3);
    // ds3: ci-split x4 -> 1024 blocks, combine (writes g_h and map_skip init)
    k_down<128, 16, 128, 2, 4, 2, 4, 128, 4><<<dim3(4, BB, 4), 128>>>(h3, wt3, nullptr, pd3, nullptr);
    k_comb3<<<2048, 256>>>(pd3, ds3b, hh, out);

    for (int i = 0; i < 4; i++) {
        k_res<<<dim3(4, BB, 4), 128>>>(hh, rwt + (size_t)i * 147456, pA);
        k_pstats<<<dim3(128, 8), 256>>>(pA);
        k_norm<<<2048, 256>>>(bn1g + i * 128, bn1b + i * 128, h3);   // h3 reused as o1
        k_res<<<dim3(4, BB, 4), 128>>>(h3, rwt + (size_t)(4 + i) * 147456, pB);
        k_pstats<<<dim3(128, 8), 256>>>(pB);
        k_applyres<<<2048, 256>>>(bn2g + i * 128, bn2b + i * 128, out);
    }

    k_fc<<<dim3(8, 16), 256, 131072>>>(fcw, fcb, out + (size_t)BB * 128 * 64);

    // re-zero scatter buffer for the next invocation (replay-safe)
    k_zero4<<<8192, 256>>>(reinterpret_cast<float4*>(scat));
}

// round 15
// speedup vs baseline: 1.1554x; 1.0168x over previous
#include <cuda_runtime.h>
#include <cuda_bf16.h>

typedef unsigned long long ull;
#define BB 64
#define NENT 512

// ---------------- device scratch ----------------
__device__ float g_scat[BB*32*4096];   // zero-initialized at load; re-zeroed at end of each launch
__device__ float g_h1[BB*32*4096];
__device__ float g_h2[BB*64*1024];
__device__ float g_h3[BB*128*256];     // reused as normalized o1 in res blocks
__device__ float g_h [BB*128*64];
__device__ float g_comb[BB*128*64];
__device__ float2 g_psum[128*8];
__device__ float g_partA[4*BB*128*64];
__device__ float g_partB[4*BB*128*64];
__device__ float g_pd2[2*BB*128*256];
__device__ float g_pd3[4*BB*128*64];
__device__ float g_wt1[32*16*64];
__device__ float g_wt2[64*16*128];
__device__ float g_wt3[128*16*128];
__device__ float g_rwt[8*128*9*128];

// ---------------- f32x2 helpers (bit-exact fp32 pairs) ----------------
__device__ __forceinline__ ull pk2(float v) {
    ull r; asm("mov.b64 %0, {%1,%2};" : "=l"(r) : "f"(v), "f"(v)); return r;
}
__device__ __forceinline__ void fma2(ull& d, ull a, ull b) {
    asm("fma.rn.f32x2 %0, %1, %2, %0;" : "+l"(d) : "l"(a), "l"(b));
}
__device__ __forceinline__ void upk(ull v, float& lo, float& hi) {
    asm("mov.b64 {%0,%1}, %2;" : "=f"(lo), "=f"(hi) : "l"(v));
}

// ---------------- small utility kernels ----------------
__global__ void k_zero4(float4* p) {
    p[blockIdx.x * 256 + threadIdx.x] = make_float4(0.f, 0.f, 0.f, 0.f);
}

// [co][ci][k16] -> [ci][k16][co]
template<int CIN, int COUT>
__global__ void k_tr_ds(const float* __restrict__ w, float* __restrict__ o) {
    int idx = blockIdx.x * 256 + threadIdx.x;
    if (idx >= CIN * 16 * COUT) return;
    int co = idx % COUT; int t = idx / COUT; int k = t % 16; int ci = t / 16;
    o[idx] = w[(co * CIN + ci) * 16 + k];
}

// res weights: [i][co][ci][k9] -> g_rwt[i'][(ci*9+k)*128+co]
__global__ void k_tr_res(const float* __restrict__ w1, const float* __restrict__ w2) {
    int idx = blockIdx.x * 256 + threadIdx.x;
    const int half = 589824;
    if (idx >= 2 * half) return;
    const float* s = (idx < half) ? w1 : w2;
    int id = (idx < half) ? idx : idx - half;
    int co = id & 127; int t = id >> 7; int k = t % 9; int t2 = t / 9;
    int ci = t2 & 127; int i = t2 >> 7;
    int dsti = (idx < half) ? i : (4 + i);
    g_rwt[(size_t)dsti * 147456 + (ci * 9 + k) * 128 + co] =
        s[(((size_t)i * 128 + co) * 128 + ci) * 9 + k];
}

// ---------------- scatter: warp per entity (R11 form; g_scat pre-zeroed) ----------------
__global__ void k_scatter(const float* __restrict__ emb, const int* __restrict__ xy,
                          const float* __restrict__ w1) {
    __shared__ float s_wT[256 * 33];
    int tid = threadIdx.x;
    for (int i = tid; i < 32 * 256; i += blockDim.x) {
        int c = i >> 8, d = i & 255;
        s_wT[d * 33 + c] = w1[i];
    }
    __syncthreads();
    int warp = blockIdx.x * (blockDim.x >> 5) + (tid >> 5);
    int lane = tid & 31;
    if (warp >= BB * NENT) return;
    int b = warp / NENT, n = warp - b * NENT;
    const int* bits = xy + (size_t)(b * NENT + n) * 16;
    if (bits[0] == -1000000000) return;
    int bit = (lane < 16) ? bits[lane] : 0;
    int contrib;
    if (lane < 8)       contrib = bit << (7 - lane);
    else if (lane < 16) contrib = bit << (31 - lane);
    else                contrib = 0;
    int pack = __reduce_add_sync(0xffffffffu, contrib);
    int xv = (pack & 0xffff) >> 2;
    int yv = (pack >> 16) >> 2;
    const float4* e4 = reinterpret_cast<const float4*>(emb + (size_t)(b * NENT + n) * 256);
    float acc = 0.f;
#pragma unroll 8
    for (int i = 0; i < 64; i++) {
        float4 v = e4[i];
        acc += v.x * s_wT[(4 * i + 0) * 33 + lane];
        acc += v.y * s_wT[(4 * i + 1) * 33 + lane];
        acc += v.z * s_wT[(4 * i + 2) * 33 + lane];
        acc += v.w * s_wT[(4 * i + 3) * 33 + lane];
    }
    acc = fmaxf(acc, 0.f);
    if (acc != 0.f)
        atomicAdd(&g_scat[((size_t)b * 32 + lane) * 4096 + yv * 64 + xv], acc);
}

// ---------------- project 1x1: thread=pixel, all 32 co, f32x2 ----------------
__global__ __launch_bounds__(256)
void k_proj(const float* __restrict__ x, const float* __restrict__ pw,
            const float* __restrict__ pb) {
    __shared__ float s_w[50 * 32];   // [ci][co]
    __shared__ float s_b[32];
    int tid = threadIdx.x;
    for (int i = tid; i < 1600; i += 256) {
        int ci = i >> 5, co = i & 31;
        s_w[i] = pw[co * 50 + ci];
    }
    if (tid < 32) s_b[tid] = pb[tid];
    __syncthreads();
    int b = blockIdx.x >> 4;
    int p = ((blockIdx.x & 15) << 8) + tid;
    ull acc[16];
#pragma unroll
    for (int g = 0; g < 16; g++) acc[g] = 0ull;
    const float* srcs = g_scat + (size_t)b * 32 * 4096 + p;
#pragma unroll 1
    for (int ci = 0; ci < 32; ci++) {
        ull vp = pk2(srcs[ci * 4096]);
        const ulonglong2* wrow = reinterpret_cast<const ulonglong2*>(&s_w[ci * 32]);
#pragma unroll
        for (int gg = 0; gg < 8; gg++) {
            ulonglong2 w2 = wrow[gg];
            fma2(acc[2 * gg], vp, w2.x);
            fma2(acc[2 * gg + 1], vp, w2.y);
        }
    }
    const float* srcx = x + (size_t)b * 18 * 4096 + p;
#pragma unroll 1
    for (int cx = 0; cx < 18; cx++) {
        ull vp = pk2(srcx[cx * 4096]);
        const ulonglong2* wrow = reinterpret_cast<const ulonglong2*>(&s_w[(32 + cx) * 32]);
#pragma unroll
        for (int gg = 0; gg < 8; gg++) {
            ulonglong2 w2 = wrow[gg];
            fma2(acc[2 * gg], vp, w2.x);
            fma2(acc[2 * gg + 1], vp, w2.y);
        }
    }
    float* dst = g_h1 + (size_t)b * 32 * 4096 + p;
#pragma unroll
    for (int g = 0; g < 16; g++) {
        float lo, hi; upk(acc[g], lo, hi);
        dst[(2 * g) * 4096]     = fmaxf(lo + s_b[2 * g], 0.f);
        dst[(2 * g + 1) * 4096] = fmaxf(hi + s_b[2 * g + 1], 0.f);
    }
}

// ---------------- down conv k=4 s=2 p=1, f32x2; CSPLIT>1 -> raw partials ----------------
// FUSEIN: input = two partial slices (stride INOFF) + bias_in + relu, fused at staging
template<int CIN, int HIN, int COUT, int TCO, int TOW, int TOH, int CC, int NTHR, int CSPLIT, bool FUSEIN>
__global__ __launch_bounds__(NTHR)
void k_down(const float* __restrict__ in, const float* __restrict__ wT,
            const float* __restrict__ bias, float* __restrict__ out,
            float* __restrict__ out2, const float* __restrict__ bias_in) {
    constexpr int HO    = HIN / 2;
    constexpr int NCOG  = COUT / TCO;
    constexpr int NROWS = 2 * TOH + 2;
    constexpr int NP    = TCO / 2;
    constexpr int CLEN  = CIN / CSPLIT;
    constexpr size_t INOFF = (size_t)BB * CIN * HIN * HIN;
    static_assert(NTHR == NCOG * (HO / TOW), "thread count");
    __shared__ float s_in[NROWS * CC * HIN];
    __shared__ float s_w[CC * 16 * COUT];
    const int tid = threadIdx.x;
    const int b = blockIdx.y, oh0 = blockIdx.x * TOH;
    const int cibase = blockIdx.z * CLEN;
    const int cog = tid % NCOG, owg = tid / NCOG;
    const int co0 = TCO * cog, ow0 = owg * TOW;
    const int ihb = 2 * oh0 - 1;
    ull acc[NP][TOH][TOW];
#pragma unroll
    for (int p = 0; p < NP; p++)
#pragma unroll
        for (int o = 0; o < TOH; o++)
#pragma unroll
            for (int w = 0; w < TOW; w++) acc[p][o][w] = 0ull;

#pragma unroll 1
    for (int c0 = 0; c0 < CLEN; c0 += CC) {
        int ci0 = cibase + c0;
        __syncthreads();
        for (int i = tid; i < NROWS * CC * (HIN / 4); i += NTHR) {
            int r   = i / (CC * (HIN / 4));
            int rem = i - r * (CC * (HIN / 4));
            int cc  = rem / (HIN / 4);
            int x4  = rem - cc * (HIN / 4);
            int ih  = ihb + r;
            float4 v = make_float4(0.f, 0.f, 0.f, 0.f);
            if (ih >= 0 && ih < HIN) {
                size_t idx4 = (((size_t)b * CIN + ci0 + cc) * HIN + ih) * HIN + 4 * x4;
                if constexpr (FUSEIN) {
                    float4 a = *reinterpret_cast<const float4*>(&in[idx4]);
                    float4 c4 = *reinterpret_cast<const float4*>(&in[INOFF + idx4]);
                    float bv = bias_in[ci0 + cc];
                    v.x = fmaxf(a.x + c4.x + bv, 0.f);
                    v.y = fmaxf(a.y + c4.y + bv, 0.f);
                    v.z = fmaxf(a.z + c4.z + bv, 0.f);
                    v.w = fmaxf(a.w + c4.w + bv, 0.f);
                } else {
                    v = *reinterpret_cast<const float4*>(&in[idx4]);
                }
            }
            *reinterpret_cast<float4*>(&s_in[(r * CC + cc) * HIN + 4 * x4]) = v;
        }
        const float4* wsrc = reinterpret_cast<const float4*>(wT + (size_t)ci0 * 16 * COUT);
        float4* wdst = reinterpret_cast<float4*>(s_w);
        for (int i = tid; i < CC * 16 * COUT / 4; i += NTHR) wdst[i] = wsrc[i];
        __syncthreads();
#pragma unroll 1
        for (int cc = 0; cc < CC; cc++) {
#pragma unroll
            for (int r = 0; r < NROWS; r++) {
                const float* row = &s_in[(r * CC + cc) * HIN];
                ull xd[2 * TOW + 2];
#pragma unroll
                for (int j = 0; j < 2 * TOW + 2; j++) {
                    int iw = 2 * ow0 - 1 + j;
                    float v = (iw >= 0 && iw < HIN) ? row[iw] : 0.f;
                    xd[j] = pk2(v);
                }
#pragma unroll
                for (int ot = 0; ot < TOH; ot++) {
                    int kh = r - 2 * ot;
                    if (kh >= 0 && kh < 4) {
                        ull wpk[NP][4];
#pragma unroll
                        for (int kw = 0; kw < 4; kw++) {
                            int idx = (cc * 16 + kh * 4 + kw) * COUT + co0;
                            if constexpr (NP == 2) {
                                ulonglong2 t = *reinterpret_cast<const ulonglong2*>(&s_w[idx]);
                                wpk[0][kw] = t.x; wpk[1][kw] = t.y;
                            } else {
                                wpk[0][kw] = *reinterpret_cast<const ull*>(&s_w[idx]);
                            }
                        }
#pragma unroll
                        for (int w = 0; w < TOW; w++)
#pragma unroll
                            for (int kw = 0; kw < 4; kw++)
#pragma unroll
                                for (int p = 0; p < NP; p++)
                                    fma2(acc[p][ot][w], xd[2 * w + kw], wpk[p][kw]);
                    }
                }
            }
        }
    }
    if constexpr (CSPLIT == 1) {
#pragma unroll
        for (int p = 0; p < NP; p++) {
            float bv0 = bias[co0 + 2 * p], bv1 = bias[co0 + 2 * p + 1];
#pragma unroll
            for (int ot = 0; ot < TOH; ot++)
#pragma unroll
                for (int w = 0; w < TOW; w++) {
                    float lo, hi; upk(acc[p][ot][w], lo, hi);
                    float v0 = fmaxf(lo + bv0, 0.f);
                    float v1 = fmaxf(hi + bv1, 0.f);
                    size_t o0 = (((size_t)b * COUT + co0 + 2 * p) * HO + oh0 + ot) * HO + ow0 + w;
                    out[o0] = v0;
                    out[o0 + (size_t)HO * HO] = v1;
                    if (out2) { out2[o0] = v0; out2[o0 + (size_t)HO * HO] = v1; }
                }
        }
    } else {
        float* dstp = out + (size_t)blockIdx.z * BB * COUT * HO * HO;
#pragma unroll
        for (int p = 0; p < NP; p++)
#pragma unroll
            for (int ot = 0; ot < TOH; ot++)
#pragma unroll
                for (int w = 0; w < TOW; w++) {
                    float lo, hi; upk(acc[p][ot][w], lo, hi);
                    size_t o0 = (((size_t)b * COUT + co0 + 2 * p) * HO + oh0 + ot) * HO + ow0 + w;
                    dstp[o0] = lo;
                    dstp[o0 + (size_t)HO * HO] = hi;
                }
    }
}

// ---------------- ds3 combine: 4 partials + bias + relu -> g_h and d_out ----------------
__global__ __launch_bounds__(256)
void k_comb3(const float* __restrict__ part, const float* __restrict__ bias,
             float* __restrict__ hh, float* __restrict__ out) {
    int idx = blockIdx.x * 256 + threadIdx.x;   // over 64*128*64
    int c = (idx >> 6) & 127;
    float v = fmaxf(part[idx] + part[524288 + idx] + part[1048576 + idx]
                    + part[1572864 + idx] + bias[c], 0.f);
    hh[idx] = v;
    out[idx] = v;
}

// ---------------- res conv 3x3 p1 on 8x8: 2 co/thread, 32co blocks, zi=4 ----------------
__global__ __launch_bounds__(128)
void k_res(const float* __restrict__ in, const float* __restrict__ wT,
           float* __restrict__ part) {
    __shared__ float s_img[16 * 100];
    __shared__ float s_w[16 * 9 * 32];   // [ciL][k][32 co]
    const int tid = threadIdx.x;
    const int b = blockIdx.y;
    const int co_base = blockIdx.x * 32;
    const int zi = blockIdx.z;
    const int copl = tid & 15, ohp = tid >> 4;
    const int co0 = co_base + 2 * copl;
    ull acc[8];
#pragma unroll
    for (int w = 0; w < 8; w++) acc[w] = 0ull;

#pragma unroll 1
    for (int c2 = 0; c2 < 2; c2++) {
        int cib = zi * 32 + c2 * 16;
        __syncthreads();
        for (int i = tid; i < 16 * 36; i += 128) {
            int ci = i / 36, e = i - 36 * ci;
            int ofs;
            if (e < 10)      ofs = e;
            else if (e < 20) ofs = 90 + (e - 10);
            else { int r = ((e - 20) >> 1) + 1; int c = ((e - 20) & 1) * 9; ofs = r * 10 + c; }
            s_img[ci * 100 + ofs] = 0.f;
        }
        {
            int ci = tid >> 3, r = tid & 7;
            const float4* src = reinterpret_cast<const float4*>(
                in + (((size_t)(b * 128 + cib + ci)) * 8 + r) * 8);
            float4 v0 = src[0], v1 = src[1];
            float* d = &s_img[ci * 100 + (r + 1) * 10 + 1];
            d[0] = v0.x; d[1] = v0.y; d[2] = v0.z; d[3] = v0.w;
            d[4] = v1.x; d[5] = v1.y; d[6] = v1.z; d[7] = v1.w;
        }
        for (int i = tid; i < 16 * 9 * 8; i += 128) {
            int c8 = i & 7; int t = i >> 3; int k = t % 9; int ciL = t / 9;
            *reinterpret_cast<float4*>(&s_w[(ciL * 9 + k) * 32 + 4 * c8]) =
                *reinterpret_cast<const float4*>(
                    wT + ((size_t)(cib + ciL) * 9 + k) * 128 + co_base + 4 * c8);
        }
        __syncthreads();
#pragma unroll 1
        for (int ciL = 0; ciL < 16; ciL++) {
            ull wp[9];
#pragma unroll
            for (int k = 0; k < 9; k++)
                wp[k] = *reinterpret_cast<const ull*>(&s_w[(ciL * 9 + k) * 32 + 2 * copl]);
#pragma unroll
            for (int kh = 0; kh < 3; kh++) {
                const float* row = &s_img[ciL * 100 + (ohp + kh) * 10];
                ull xd[10];
#pragma unroll
                for (int j = 0; j < 10; j++) xd[j] = pk2(row[j]);
#pragma unroll
                for (int ow = 0; ow < 8; ow++)
#pragma unroll
                    for (int kw = 0; kw < 3; kw++)
                        fma2(acc[ow], xd[ow + kw], wp[kh * 3 + kw]);
            }
        }
    }
    float* dst = part + (size_t)zi * 524288 + ((size_t)(b * 128 + co0)) * 64 + ohp * 8;
#pragma unroll
    for (int ow = 0; ow < 8; ow++) {
        float lo, hi; upk(acc[ow], lo, hi);
        dst[ow] = lo; dst[64 + ow] = hi;
    }
}

// ---------------- stage A: combine 4 partials, per-(channel,slice) stats ----------------
__global__ __launch_bounds__(256)
void k_pstats(const float* __restrict__ part) {
    int c = blockIdx.x, s = blockIdx.y, tid = threadIdx.x;
    float sum = 0.f, sq = 0.f;
#pragma unroll
    for (int t = 0; t < 2; t++) {
        int i = s * 512 + t * 256 + tid;       // i = b*64 + p
        int b = i >> 6, p = i & 63;
        size_t idx = ((size_t)(b * 128 + c)) * 64 + p;
        float v = part[idx] + part[524288 + idx] + part[1048576 + idx] + part[1572864 + idx];
        g_comb[idx] = v;
        sum += v; sq += v * v;
    }
    __shared__ float rs[256], rs2[256];
    rs[tid] = sum; rs2[tid] = sq;
    __syncthreads();
    for (int o = 128; o > 0; o >>= 1) {
        if (tid < o) { rs[tid] += rs[tid + o]; rs2[tid] += rs2[tid + o]; }
        __syncthreads();
    }
    if (tid == 0) g_psum[c * 8 + s] = make_float2(rs[0], rs2[0]);
}

// ---------------- stage B: fold psum -> scale/shift, normalize + relu ----------------
__global__ __launch_bounds__(256)
void k_norm(const float* __restrict__ gamma, const float* __restrict__ beta,
            float* __restrict__ o1) {
    int idx = blockIdx.x * 256 + threadIdx.x;
    int c = (idx >> 6) & 127;
    float s = 0.f, s2 = 0.f;
#pragma unroll
    for (int q = 0; q < 8; q++) {
        float2 v = g_psum[c * 8 + q];
        s += v.x; s2 += v.y;
    }
    float mean = s / 4096.f;
    float var  = s2 / 4096.f - mean * mean;
    float sc   = gamma[c] * rsqrtf(var + 1e-5f);
    float sh   = beta[c] - mean * sc;
    o1[idx] = fmaxf(fmaf(sc, g_comb[idx], sh), 0.f);
}

// ---------------- stage B': fold psum, normalize + residual + relu; g_h, map_skip ----------------
__global__ __launch_bounds__(256)
void k_applyres(const float* __restrict__ gamma, const float* __restrict__ beta,
                float* __restrict__ dskip) {
    int idx = blockIdx.x * 256 + threadIdx.x;
    int c = (idx >> 6) & 127;
    float s = 0.f, s2 = 0.f;
#pragma unroll
    for (int q = 0; q < 8; q++) {
        float2 v = g_psum[c * 8 + q];
        s += v.x; s2 += v.y;
    }
    float mean = s / 4096.f;
    float var  = s2 / 4096.f - mean * mean;
    float sc   = gamma[c] * rsqrtf(var + 1e-5f);
    float sh   = beta[c] - mean * sc;
    float h = fmaxf(fmaf(sc, g_comb[idx], sh) + g_h[idx], 0.f);
    g_h[idx] = h;
    dskip[idx] += h;
}

// ---------------- fc: 4 b rows in dynamic smem, 32 j per block ----------------
__global__ __launch_bounds__(256)
void k_fc(const float* __restrict__ w, const float* __restrict__ bias,
          float* __restrict__ outp) {
    extern __shared__ float s_a[];   // 4 * 8192
    int b0 = blockIdx.y * 4;
    int tid = threadIdx.x;
    float4* sd = reinterpret_cast<float4*>(s_a);
    const float4* src = reinterpret_cast<const float4*>(g_h + (size_t)b0 * 8192);
    for (int i = tid; i < 8192; i += 256) sd[i] = src[i];
    __syncthreads();
    int wrp = tid >> 5, lane = tid & 31;
#pragma unroll 1
    for (int q = 0; q < 4; q++) {
        int j = blockIdx.x * 32 + wrp * 4 + q;
        const float4* wr = reinterpret_cast<const float4*>(w + (size_t)j * 8192);
        float acc[4];
#pragma unroll
        for (int bl = 0; bl < 4; bl++) acc[bl] = 0.f;
#pragma unroll 2
        for (int i = lane; i < 2048; i += 32) {
            float4 wv = wr[i];
#pragma unroll
            for (int bl = 0; bl < 4; bl++) {
                float4 av = sd[bl * 2048 + i];
                acc[bl] += wv.x * av.x + wv.y * av.y + wv.z * av.z + wv.w * av.w;
            }
        }
#pragma unroll
        for (int o = 16; o > 0; o >>= 1)
#pragma unroll
            for (int bl = 0; bl < 4; bl++)
                acc[bl] += __shfl_down_sync(0xffffffffu, acc[bl], o);
        if (lane == 0) {
            float bv = bias[j];
#pragma unroll
            for (int bl = 0; bl < 4; bl++)
                outp[(size_t)(b0 + bl) * 256 + j] = fmaxf(acc[bl] + bv, 0.f);
        }
    }
}

// ---------------- launch ----------------
extern "C" void kernel_launch(void* const* d_in, const int* in_sizes, int n_in,
                              void* d_out, int out_size) {
    const float* x    = (const float*)d_in[0];
    const float* emb  = (const float*)d_in[1];
    const int*   xy   = (const int*)  d_in[2];
    const float* c1w  = (const float*)d_in[3];
    const float* pw   = (const float*)d_in[4];
    const float* pb   = (const float*)d_in[5];
    const float* ds1w = (const float*)d_in[6];
    const float* ds1b = (const float*)d_in[7];
    const float* ds2w = (const float*)d_in[8];
    const float* ds2b = (const float*)d_in[9];
    const float* ds3w = (const float*)d_in[10];
    const float* ds3b = (const float*)d_in[11];
    const float* rc1w = (const float*)d_in[12];
    const float* bn1g = (const float*)d_in[13];
    const float* bn1b = (const float*)d_in[14];
    const float* rc2w = (const float*)d_in[15];
    const float* bn2g = (const float*)d_in[16];
    const float* bn2b = (const float*)d_in[17];
    const float* fcw  = (const float*)d_in[18];
    const float* fcb  = (const float*)d_in[19];
    float* out = (float*)d_out;

    float *scat, *h1, *h2, *h3, *hh, *pA, *pB, *pd2, *pd3, *wt1, *wt2, *wt3, *rwt;
    cudaGetSymbolAddress((void**)&scat, g_scat);
    cudaGetSymbolAddress((void**)&h1,   g_h1);
    cudaGetSymbolAddress((void**)&h2,   g_h2);
    cudaGetSymbolAddress((void**)&h3,   g_h3);
    cudaGetSymbolAddress((void**)&hh,   g_h);
    cudaGetSymbolAddress((void**)&pA,   g_partA);
    cudaGetSymbolAddress((void**)&pB,   g_partB);
    cudaGetSymbolAddress((void**)&pd2,  g_pd2);
    cudaGetSymbolAddress((void**)&pd3,  g_pd3);
    cudaGetSymbolAddress((void**)&wt1,  g_wt1);
    cudaGetSymbolAddress((void**)&wt2,  g_wt2);
    cudaGetSymbolAddress((void**)&wt3,  g_wt3);
    cudaGetSymbolAddress((void**)&rwt,  g_rwt);

    cudaFuncSetAttribute((const void*)k_fc, cudaFuncAttributeMaxDynamicSharedMemorySize, 131072);

    // order chosen so launch #4 (profiled slot) = ds1
    k_tr_ds<32, 64><<<(32 * 16 * 64 + 255) / 256, 256>>>(ds1w, wt1);          // 1
    k_scatter<<<(BB * NENT) / 8, 256>>>(emb, xy, c1w);                        // 2 (g_scat pre-zeroed)
    k_proj<<<1024, 256>>>(x, pw, pb);                                         // 3
    // ds1: converged R11 config — CSPLIT=1, direct epilogue
    k_down<32, 64, 64, 4, 4, 2, 4, 128, 1, false><<<dim3(16, BB), 128>>>(
        h1, wt1, ds1b, h2, nullptr, nullptr);                                 // 4 <- profiled

    k_tr_ds<64, 128> <<<(64 * 16 * 128 + 255) / 256, 256>>>(ds2w, wt2);
    k_tr_ds<128, 128><<<(128 * 16 * 128 + 255) / 256, 256>>>(ds3w, wt3);
    k_tr_res<<<(2 * 589824 + 255) / 256, 256>>>(rc1w, rc2w);

    // ds2: ci-split x2 -> 1024 blocks, raw partials to pd2 (no combine kernel)
    k_down<64, 32, 128, 4, 4, 2, 4, 128, 2, false><<<dim3(8, BB, 2), 128>>>(
        h2, wt2, nullptr, pd2, nullptr, nullptr);
    // ds3: reads pd2 partials directly (bias+relu fused into staging); ci-split x4
    k_down<128, 16, 128, 2, 4, 2, 4, 128, 4, true><<<dim3(4, BB, 4), 128>>>(
        pd2, wt3, nullptr, pd3, nullptr, ds2b);
    k_comb3<<<2048, 256>>>(pd3, ds3b, hh, out);

    for (int i = 0; i < 4; i++) {
        k_res<<<dim3(4, BB, 4), 128>>>(hh, rwt + (size_t)i * 147456, pA);
        k_pstats<<<dim3(128, 8), 256>>>(pA);
        k_norm<<<2048, 256>>>(bn1g + i * 128, bn1b + i * 128, h3);   // h3 reused as o1
        k_res<<<dim3(4, BB, 4), 128>>>(h3, rwt + (size_t)(4 + i) * 147456, pB);
        k_pstats<<<dim3(128, 8), 256>>>(pB);
        k_applyres<<<2048, 256>>>(bn2g + i * 128, bn2b + i * 128, out);
    }

    k_fc<<<dim3(8, 16), 256, 131072>>>(fcw, fcb, out + (size_t)BB * 128 * 64);

    // re-zero scatter buffer for the next invocation (replay-safe)
    k_zero4<<<8192, 256>>>(reinterpret_cast<float4*>(scat));
}